// round 4
// baseline (speedup 1.0000x reference)
#include <cuda_runtime.h>
#include <cuda_bf16.h>
#include <cstdint>

#define HD   2048
#define SEQ  2048
#define NB   4
#define TOK  (NB*SEQ)
#define KDIM 2048
#define BM   128
#define BN   256
#define BK   64                 // bf16 elems = 128 bytes per row
#define KITERS (KDIM/BK)        // 32

typedef __nv_bfloat16 bf16;

// ---------------- static device scratch --------------------------------------
__device__ bf16  g_xh[(size_t)TOK*HD],  g_xl[(size_t)TOK*HD];
__device__ bf16  g_wqh[(size_t)HD*HD],  g_wql[(size_t)HD*HD];
__device__ bf16  g_wkh[(size_t)HD*HD],  g_wkl[(size_t)HD*HD];
__device__ bf16  g_wvh[(size_t)HD*HD],  g_wvl[(size_t)HD*HD];
__device__ bf16  g_w1h[(size_t)HD*HD],  g_w1l[(size_t)HD*HD];
__device__ bf16  g_woth[(size_t)HD*HD], g_wotl[(size_t)HD*HD];
__device__ bf16  g_wfh[(size_t)HD*HD],  g_wfl[(size_t)HD*HD];
__device__ bf16  g_qh[(size_t)TOK*HD],  g_ql[(size_t)TOK*HD];
__device__ bf16  g_kh[(size_t)TOK*HD],  g_kl[(size_t)TOK*HD];
__device__ float g_vf[(size_t)TOK*HD];
__device__ bf16  g_vth[(size_t)TOK*HD], g_vtl[(size_t)TOK*HD];
__device__ float g_sc[(size_t)NB*SEQ*SEQ];
__device__ bf16  g_ph[(size_t)NB*SEQ*SEQ], g_pl[(size_t)NB*SEQ*SEQ];
__device__ bf16  g_ath[(size_t)TOK*HD], g_atl[(size_t)TOK*HD];
__device__ float g_w2s[HD];
__device__ double g_acc;

// ---------------- helpers -----------------------------------------------------
__device__ __forceinline__ uint32_t s2u(const void* p){
    uint32_t a;
    asm("{ .reg .u64 t; cvta.to.shared.u64 t, %1; cvt.u32.u64 %0, t; }" : "=r"(a) : "l"(p));
    return a;
}
__device__ __forceinline__ uint32_t pk(bf16 a, bf16 b){
    __nv_bfloat162 t(a, b); return *reinterpret_cast<uint32_t*>(&t);
}

#define CPA(dst, src) asm volatile("cp.async.cg.shared.global [%0], [%1], 16;" \
    :: "r"(dst), "l"(src) : "memory")
#define CPA_COMMIT() asm volatile("cp.async.commit_group;" ::: "memory")
#define CPA_WAIT1()  asm volatile("cp.async.wait_group 1;" ::: "memory")
#define CPA_WAIT0()  asm volatile("cp.async.wait_group 0;" ::: "memory")

__device__ __forceinline__ void ldm4(uint32_t* r, uint32_t addr){
    asm volatile("ldmatrix.sync.aligned.m8n8.x4.shared.b16 {%0,%1,%2,%3}, [%4];"
        : "=r"(r[0]), "=r"(r[1]), "=r"(r[2]), "=r"(r[3]) : "r"(addr));
}
__device__ __forceinline__ void mma_bf16(float* d, const uint32_t* a, const uint32_t* b){
    asm volatile(
        "mma.sync.aligned.m16n8k16.row.col.f32.bf16.bf16.f32 "
        "{%0,%1,%2,%3}, {%4,%5,%6,%7}, {%8,%9}, {%0,%1,%2,%3};"
        : "+f"(d[0]), "+f"(d[1]), "+f"(d[2]), "+f"(d[3])
        : "r"(a[0]), "r"(a[1]), "r"(a[2]), "r"(a[3]), "r"(b[0]), "r"(b[1]));
}

// SMEM stage: Ah @0 (16K), Al @16K, Bh @32K (32K), Bl @64K (32K); stage 96K; 2 stages
#define A_TILE_B 16384
#define B_TILE_B 32768
#define STAGE_B  98304
#define SMEM_TOT (2*STAGE_B)

// ---------------- split-bf16 mma.sync GEMM ------------------------------------
// C[m,n] = sum_k A[m,k]*B[n,k]  (NT), K=2048, all leading dims 2048.
// MODE 0: write split bf16 (Ch,Cl); 1: write fp32 Cf; 2: sum(relu(C)*w2s)->g_acc
template<int MODE>
__global__ void __launch_bounds__(256, 1) mma_gemm(
    const bf16* __restrict__ Ah, const bf16* __restrict__ Al,
    const bf16* __restrict__ Bh, const bf16* __restrict__ Bl,
    bf16* __restrict__ Ch, bf16* __restrict__ Cl, float* __restrict__ Cf,
    const float* __restrict__ w2s,
    size_t sA, size_t sB, size_t sC)
{
    extern __shared__ char smem[];
    const uint32_t sb = s2u(smem);

    const int tid = threadIdx.x;
    const int l   = tid & 31;
    const int wid = tid >> 5;
    const int wm  = wid & 1;          // 2 warps along M (64 rows each)
    const int wn  = wid >> 1;         // 4 warps along N (64 cols each)
    const int bn  = blockIdx.x * BN;
    const int bm  = blockIdx.y * BM;
    const size_t zo = blockIdx.z;

    Ah += zo * sA;  Al += zo * sA;
    Bh += zo * sB;  Bl += zo * sB;

    // ---- producer (cp.async) addressing
    const int pr = tid >> 3;                 // 0..31 base row
    const int pc = (tid & 7) * 16;           // byte col in 128B row
    const uint32_t pdst = (uint32_t)pr * 128u + ((uint32_t)pc ^ (((uint32_t)pr & 7u) << 4));
    const char* gAh = (const char*)(Ah + (size_t)(bm + pr) * KDIM) + pc;
    const char* gAl = (const char*)(Al + (size_t)(bm + pr) * KDIM) + pc;
    const char* gBh = (const char*)(Bh + (size_t)(bn + pr) * KDIM) + pc;
    const char* gBl = (const char*)(Bl + (size_t)(bn + pr) * KDIM) + pc;

    // ---- consumer (ldmatrix) addressing
    const int ar    = wm * 64 + (l & 15);
    const int akoff = (l >> 4) * 16;
    const uint32_t xA = ((uint32_t)ar & 7u) << 4;
    const int br    = wn * 64 + (l & 7) + ((l >> 4) & 1) * 8;   // + p*16
    const int bkoff = ((l >> 3) & 1) * 16;
    const uint32_t xB = ((uint32_t)br & 7u) << 4;

    float acc[4][8][4];
    #pragma unroll
    for (int i = 0; i < 4; i++)
        #pragma unroll
        for (int j = 0; j < 8; j++)
            #pragma unroll
            for (int r = 0; r < 4; r++) acc[i][j][r] = 0.f;

    // ---- issue stage 0
    {
        const uint32_t s0 = sb;
        #pragma unroll
        for (int j = 0; j < 4; j++){
            const size_t go = (size_t)j * 131072;     // +32 rows
            CPA(s0 +            pdst + j*4096, gAh + go);
            CPA(s0 + A_TILE_B + pdst + j*4096, gAl + go);
        }
        #pragma unroll
        for (int j = 0; j < 8; j++){
            const size_t go = (size_t)j * 131072;
            CPA(s0 + 2*A_TILE_B            + pdst + j*4096, gBh + go);
            CPA(s0 + 2*A_TILE_B + B_TILE_B + pdst + j*4096, gBl + go);
        }
        CPA_COMMIT();
    }

    #pragma unroll 1
    for (int i = 0; i < KITERS; i++){
        if (i + 1 < KITERS){
            const uint32_t s0 = sb + (uint32_t)((i + 1) & 1) * STAGE_B;
            const size_t ko = (size_t)(i + 1) * 128;
            #pragma unroll
            for (int j = 0; j < 4; j++){
                const size_t go = (size_t)j * 131072 + ko;
                CPA(s0 +            pdst + j*4096, gAh + go);
                CPA(s0 + A_TILE_B + pdst + j*4096, gAl + go);
            }
            #pragma unroll
            for (int j = 0; j < 8; j++){
                const size_t go = (size_t)j * 131072 + ko;
                CPA(s0 + 2*A_TILE_B            + pdst + j*4096, gBh + go);
                CPA(s0 + 2*A_TILE_B + B_TILE_B + pdst + j*4096, gBl + go);
            }
            CPA_COMMIT();
            CPA_WAIT1();
        } else {
            CPA_WAIT0();
        }
        __syncthreads();

        const uint32_t s0 = sb + (uint32_t)(i & 1) * STAGE_B;
        #pragma unroll
        for (int ks = 0; ks < 4; ks++){
            const uint32_t kb = (uint32_t)ks * 32;
            uint32_t ah[4][4], al[4][4];
            #pragma unroll
            for (int fm = 0; fm < 4; fm++){
                uint32_t ad = s0 + (uint32_t)(ar + fm*16) * 128u + ((kb + akoff) ^ xA);
                ldm4(ah[fm], ad);
                ldm4(al[fm], ad + A_TILE_B);
            }
            #pragma unroll
            for (int p = 0; p < 4; p++){            // 16 B-rows per p -> 2 fn
                uint32_t bh[4], bl[4];
                uint32_t bd = s0 + 2*A_TILE_B + (uint32_t)(br + p*16) * 128u + ((kb + bkoff) ^ xB);
                ldm4(bh, bd);
                ldm4(bl, bd + B_TILE_B);
                #pragma unroll
                for (int fm = 0; fm < 4; fm++){
                    #pragma unroll
                    for (int h = 0; h < 2; h++){
                        float* d = acc[fm][2*p + h];
                        mma_bf16(d, ah[fm], &bh[2*h]);   // hi*hi
                        mma_bf16(d, ah[fm], &bl[2*h]);   // hi*lo
                        mma_bf16(d, al[fm], &bh[2*h]);   // lo*hi
                    }
                }
            }
        }
        __syncthreads();
    }

    // ---- epilogue
    const int crow = l >> 2;
    const int ccol = (l & 3) * 2;
    double local = 0.0;

    #pragma unroll
    for (int fm = 0; fm < 4; fm++){
        #pragma unroll
        for (int fn = 0; fn < 8; fn++){
            const int m0 = bm + wm*64 + fm*16 + crow;
            const int n0 = bn + wn*64 + fn*8 + ccol;
            const float* c = acc[fm][fn];
            if (MODE == 1){
                float* base = Cf + zo*sC;
                *(float2*)(base + (size_t)m0 * KDIM + n0)       = make_float2(c[0], c[1]);
                *(float2*)(base + (size_t)(m0+8) * KDIM + n0)   = make_float2(c[2], c[3]);
            } else if (MODE == 0){
                const size_t o0 = zo*sC + (size_t)m0 * KDIM + n0;
                const size_t o1 = zo*sC + (size_t)(m0+8) * KDIM + n0;
                #pragma unroll
                for (int h = 0; h < 2; h++){
                    float f0 = c[2*h], f1 = c[2*h+1];
                    bf16 h0 = __float2bfloat16_rn(f0);
                    bf16 h1 = __float2bfloat16_rn(f1);
                    bf16 l0 = __float2bfloat16_rn(f0 - __bfloat162float(h0));
                    bf16 l1 = __float2bfloat16_rn(f1 - __bfloat162float(h1));
                    size_t o = h ? o1 : o0;
                    *(uint32_t*)(Ch + o) = pk(h0, h1);
                    *(uint32_t*)(Cl + o) = pk(l0, l1);
                }
            } else {
                float w0 = w2s[n0], w1 = w2s[n0+1];
                float z;
                z = c[0]; local += (double)((z > 0.f ? z : 0.f) * w0);
                z = c[1]; local += (double)((z > 0.f ? z : 0.f) * w1);
                z = c[2]; local += (double)((z > 0.f ? z : 0.f) * w0);
                z = c[3]; local += (double)((z > 0.f ? z : 0.f) * w1);
            }
        }
    }

    if (MODE == 2){
        __syncthreads();
        double* red = (double*)smem;
        red[tid] = local;
        __syncthreads();
        #pragma unroll
        for (int s = 128; s > 0; s >>= 1){
            if (tid < s) red[tid] += red[tid + s];
            __syncthreads();
        }
        if (tid == 0) atomicAdd(&g_acc, red[0]);
    }
}

// ---------------- aux kernels -------------------------------------------------
__global__ void csplit_k(const float4* __restrict__ in, uint2* __restrict__ oh,
                         uint2* __restrict__ ol)
{
    size_t i = (size_t)blockIdx.x * 256 + threadIdx.x;
    float4 f = in[i];
    bf16 h0 = __float2bfloat16_rn(f.x), h1 = __float2bfloat16_rn(f.y);
    bf16 h2 = __float2bfloat16_rn(f.z), h3 = __float2bfloat16_rn(f.w);
    bf16 l0 = __float2bfloat16_rn(f.x - __bfloat162float(h0));
    bf16 l1 = __float2bfloat16_rn(f.y - __bfloat162float(h1));
    bf16 l2 = __float2bfloat16_rn(f.z - __bfloat162float(h2));
    bf16 l3 = __float2bfloat16_rn(f.w - __bfloat162float(h3));
    oh[i] = make_uint2(pk(h0,h1), pk(h2,h3));
    ol[i] = make_uint2(pk(l0,l1), pk(l2,l3));
}

// out[C][R] = in[R][C], split bf16 hi/lo; grid (C/32, R/32, z), block (32,8)
__global__ void tsplit_k(const float* __restrict__ in, bf16* __restrict__ oh,
                         bf16* __restrict__ ol, int R, int C, size_t sI, size_t sO)
{
    __shared__ float t[32][33];
    const float* src = in + (size_t)blockIdx.z * sI;
    int c0 = blockIdx.x * 32, r0 = blockIdx.y * 32;
    int tx = threadIdx.x, ty = threadIdx.y;
    #pragma unroll
    for (int j = 0; j < 32; j += 8)
        t[ty + j][tx] = src[(size_t)(r0 + ty + j) * C + c0 + tx];
    __syncthreads();
    #pragma unroll
    for (int j = 0; j < 32; j += 8){
        float f = t[tx][ty + j];
        bf16 h = __float2bfloat16_rn(f);
        bf16 lo = __float2bfloat16_rn(f - __bfloat162float(h));
        size_t o = (size_t)blockIdx.z * sO + (size_t)(c0 + ty + j) * R + r0 + tx;
        oh[o] = h;  ol[o] = lo;
    }
}

__global__ void softmax_k(const float* __restrict__ S, bf16* __restrict__ Ph,
                          bf16* __restrict__ Pl)
{
    const float* row = S + (size_t)blockIdx.x * SEQ;
    bf16* ph = Ph + (size_t)blockIdx.x * SEQ;
    bf16* pl = Pl + (size_t)blockIdx.x * SEQ;
    const int tid = threadIdx.x;  // 256
    __shared__ float sm[256];

    float v[8];
    float mx = -3.0e38f;
    #pragma unroll
    for (int t = 0; t < 8; t++){ v[t] = row[tid + 256*t]; mx = fmaxf(mx, v[t]); }
    sm[tid] = mx; __syncthreads();
    #pragma unroll
    for (int s = 128; s > 0; s >>= 1){
        if (tid < s) sm[tid] = fmaxf(sm[tid], sm[tid + s]);
        __syncthreads();
    }
    mx = sm[0]; __syncthreads();

    float sum = 0.f;
    #pragma unroll
    for (int t = 0; t < 8; t++){ v[t] = expf(v[t] - mx); sum += v[t]; }
    sm[tid] = sum; __syncthreads();
    #pragma unroll
    for (int s = 128; s > 0; s >>= 1){
        if (tid < s) sm[tid] += sm[tid + s];
        __syncthreads();
    }
    float inv = 1.0f / sm[0];
    #pragma unroll
    for (int t = 0; t < 8; t++){
        float f = v[t] * inv;
        bf16 h = __float2bfloat16_rn(f);
        bf16 lo = __float2bfloat16_rn(f - __bfloat162float(h));
        ph[tid + 256*t] = h;  pl[tid + 256*t] = lo;
    }
}

__global__ void w2sum_k(const float* __restrict__ W2)
{
    int e = blockIdx.x * 256 + threadIdx.x;
    float s = 0.f;
    for (int d = 0; d < HD; d++) s += W2[(size_t)d * HD + e];
    g_w2s[e] = s;
}

__global__ void zero_k(){ g_acc = 0.0; }
__global__ void out_k(float* __restrict__ out){ out[0] = (float)g_acc; }

// ---------------- launch --------------------------------------------------------
extern "C" void kernel_launch(void* const* d_in, const int* in_sizes, int n_in,
                              void* d_out, int out_size)
{
    const float* x  = (const float*)d_in[0];
    const float* Wq = (const float*)d_in[1];
    const float* Wk = (const float*)d_in[2];
    const float* Wv = (const float*)d_in[3];
    const float* Wo = (const float*)d_in[4];
    const float* W1 = (const float*)d_in[5];
    const float* W2 = (const float*)d_in[6];

    cudaFuncSetAttribute(mma_gemm<0>, cudaFuncAttributeMaxDynamicSharedMemorySize, SMEM_TOT);
    cudaFuncSetAttribute(mma_gemm<1>, cudaFuncAttributeMaxDynamicSharedMemorySize, SMEM_TOT);
    cudaFuncSetAttribute(mma_gemm<2>, cudaFuncAttributeMaxDynamicSharedMemorySize, SMEM_TOT);

    bf16 *xh,*xl,*wqh,*wql,*wkh,*wkl,*wvh,*wvl,*w1h,*w1l,*woth,*wotl,*wfh,*wfl;
    bf16 *qh,*ql,*kh,*kl,*vth,*vtl,*ph,*pl,*ath,*atl;
    float *vf,*sc,*w2s;
    cudaGetSymbolAddress((void**)&xh, g_xh);   cudaGetSymbolAddress((void**)&xl, g_xl);
    cudaGetSymbolAddress((void**)&wqh, g_wqh); cudaGetSymbolAddress((void**)&wql, g_wql);
    cudaGetSymbolAddress((void**)&wkh, g_wkh); cudaGetSymbolAddress((void**)&wkl, g_wkl);
    cudaGetSymbolAddress((void**)&wvh, g_wvh); cudaGetSymbolAddress((void**)&wvl, g_wvl);
    cudaGetSymbolAddress((void**)&w1h, g_w1h); cudaGetSymbolAddress((void**)&w1l, g_w1l);
    cudaGetSymbolAddress((void**)&woth, g_woth); cudaGetSymbolAddress((void**)&wotl, g_wotl);
    cudaGetSymbolAddress((void**)&wfh, g_wfh); cudaGetSymbolAddress((void**)&wfl, g_wfl);
    cudaGetSymbolAddress((void**)&qh, g_qh);   cudaGetSymbolAddress((void**)&ql, g_ql);
    cudaGetSymbolAddress((void**)&kh, g_kh);   cudaGetSymbolAddress((void**)&kl, g_kl);
    cudaGetSymbolAddress((void**)&vth, g_vth); cudaGetSymbolAddress((void**)&vtl, g_vtl);
    cudaGetSymbolAddress((void**)&ph, g_ph);   cudaGetSymbolAddress((void**)&pl, g_pl);
    cudaGetSymbolAddress((void**)&ath, g_ath); cudaGetSymbolAddress((void**)&atl, g_atl);
    cudaGetSymbolAddress((void**)&vf, g_vf);
    cudaGetSymbolAddress((void**)&sc, g_sc);
    cudaGetSymbolAddress((void**)&w2s, g_w2s);

    const size_t SH = (size_t)SEQ * HD;
    const size_t SS = (size_t)SEQ * SEQ;
    dim3 t8(32, 8);

    zero_k<<<1,1>>>();
    w2sum_k<<<HD/256, 256>>>(W2);

    // split fp32 -> bf16 hi/lo
    csplit_k<<<(int)((size_t)TOK*HD/1024), 256>>>((const float4*)x,  (uint2*)xh,  (uint2*)xl);
    csplit_k<<<HD*HD/1024, 256>>>((const float4*)Wq, (uint2*)wqh, (uint2*)wql);
    csplit_k<<<HD*HD/1024, 256>>>((const float4*)Wk, (uint2*)wkh, (uint2*)wkl);
    csplit_k<<<HD*HD/1024, 256>>>((const float4*)Wv, (uint2*)wvh, (uint2*)wvl);
    csplit_k<<<HD*HD/1024, 256>>>((const float4*)W1, (uint2*)w1h, (uint2*)w1l);
    tsplit_k<<<dim3(HD/32, HD/32, 1), t8>>>(Wo, woth, wotl, HD, HD, 0, 0);

    // q = x Wq^T, k = x Wk^T (split out), v = x Wv^T (fp32 out)
    dim3 gTok(HD/BN, TOK/BM, 1);
    mma_gemm<0><<<gTok, 256, SMEM_TOT>>>(xh, xl, wqh, wql, qh, ql, nullptr, nullptr, 0,0,0);
    mma_gemm<0><<<gTok, 256, SMEM_TOT>>>(xh, xl, wkh, wkl, kh, kl, nullptr, nullptr, 0,0,0);
    mma_gemm<1><<<gTok, 256, SMEM_TOT>>>(xh, xl, wvh, wvl, nullptr, nullptr, vf, nullptr, 0,0,0);

    // Wf = W1 @ Wo  (NT against Wo^T)
    dim3 gW(HD/BN, HD/BM, 1);
    mma_gemm<0><<<gW, 256, SMEM_TOT>>>(w1h, w1l, woth, wotl, wfh, wfl, nullptr, nullptr, 0,0,0);

    // v^T per batch
    tsplit_k<<<dim3(HD/32, SEQ/32, NB), t8>>>(vf, vth, vtl, SEQ, HD, SH, SH);

    // scores = q k^T per batch (fp32 out)
    dim3 gSc(SEQ/BN, SEQ/BM, NB);
    mma_gemm<1><<<gSc, 256, SMEM_TOT>>>(qh, ql, kh, kl, nullptr, nullptr, sc, nullptr, SH, SH, SS);

    softmax_k<<<NB*SEQ, 256>>>(sc, ph, pl);

    // attn = P @ v  (NT against v^T), split out
    dim3 gAt(HD/BN, SEQ/BM, NB);
    mma_gemm<0><<<gAt, 256, SMEM_TOT>>>(ph, pl, vth, vtl, ath, atl, nullptr, nullptr, SS, SH, SH);

    // final: Z = attn Wf^T, reduce sum(relu(Z) * w2sum)
    dim3 gFin(HD/BN, TOK/BM, 1);
    mma_gemm<2><<<gFin, 256, SMEM_TOT>>>(ath, atl, wfh, wfl, nullptr, nullptr, nullptr, w2s, 0,0,0);

    out_k<<<1,1>>>((float*)d_out);
}

// round 5
// speedup vs baseline: 1.0961x; 1.0961x over previous
#include <cuda_runtime.h>
#include <cuda_bf16.h>
#include <cstdint>

#define HD   2048
#define SEQ  2048
#define NB   4
#define TOK  (NB*SEQ)
#define KDIM 2048
#define BM   128
#define BN   128
#define BK   64                 // bf16 elems = 128 bytes per row
#define KITERS (KDIM/BK)        // 32

typedef __nv_bfloat16 bf16;

// ---------------- static device scratch --------------------------------------
__device__ bf16  g_xh[(size_t)TOK*HD],  g_xl[(size_t)TOK*HD];
__device__ bf16  g_wqh[(size_t)HD*HD],  g_wql[(size_t)HD*HD];
__device__ bf16  g_wkh[(size_t)HD*HD],  g_wkl[(size_t)HD*HD];
__device__ bf16  g_wvh[(size_t)HD*HD],  g_wvl[(size_t)HD*HD];
__device__ bf16  g_w1h[(size_t)HD*HD],  g_w1l[(size_t)HD*HD];
__device__ bf16  g_woth[(size_t)HD*HD], g_wotl[(size_t)HD*HD];
__device__ bf16  g_wfh[(size_t)HD*HD],  g_wfl[(size_t)HD*HD];
__device__ bf16  g_qh[(size_t)TOK*HD],  g_ql[(size_t)TOK*HD];
__device__ bf16  g_kh[(size_t)TOK*HD],  g_kl[(size_t)TOK*HD];
__device__ float g_vf[(size_t)TOK*HD];
__device__ bf16  g_vth[(size_t)TOK*HD], g_vtl[(size_t)TOK*HD];
__device__ float g_sc[(size_t)NB*SEQ*SEQ];
__device__ bf16  g_ph[(size_t)NB*SEQ*SEQ], g_pl[(size_t)NB*SEQ*SEQ];
__device__ bf16  g_ath[(size_t)TOK*HD], g_atl[(size_t)TOK*HD];
__device__ float g_w2s[HD];
__device__ double g_acc;

// ---------------- helpers -----------------------------------------------------
__device__ __forceinline__ uint32_t s2u(const void* p){
    uint32_t a;
    asm("{ .reg .u64 t; cvta.to.shared.u64 t, %1; cvt.u32.u64 %0, t; }" : "=r"(a) : "l"(p));
    return a;
}
__device__ __forceinline__ uint32_t pk(bf16 a, bf16 b){
    __nv_bfloat162 t(a, b); return *reinterpret_cast<uint32_t*>(&t);
}

#define CPA(dst, src) asm volatile("cp.async.cg.shared.global [%0], [%1], 16;" \
    :: "r"(dst), "l"(src) : "memory")
#define CPA_COMMIT() asm volatile("cp.async.commit_group;" ::: "memory")
#define CPA_WAIT2()  asm volatile("cp.async.wait_group 2;" ::: "memory")
#define CPA_WAIT1()  asm volatile("cp.async.wait_group 1;" ::: "memory")
#define CPA_WAIT0()  asm volatile("cp.async.wait_group 0;" ::: "memory")

__device__ __forceinline__ void ldm4(uint32_t* r, uint32_t addr){
    asm volatile("ldmatrix.sync.aligned.m8n8.x4.shared.b16 {%0,%1,%2,%3}, [%4];"
        : "=r"(r[0]), "=r"(r[1]), "=r"(r[2]), "=r"(r[3]) : "r"(addr));
}
__device__ __forceinline__ void mma_bf16(float* d, const uint32_t* a, const uint32_t* b){
    asm volatile(
        "mma.sync.aligned.m16n8k16.row.col.f32.bf16.bf16.f32 "
        "{%0,%1,%2,%3}, {%4,%5,%6,%7}, {%8,%9}, {%0,%1,%2,%3};"
        : "+f"(d[0]), "+f"(d[1]), "+f"(d[2]), "+f"(d[3])
        : "r"(a[0]), "r"(a[1]), "r"(a[2]), "r"(a[3]), "r"(b[0]), "r"(b[1]));
}

// SMEM stage: Ah @0, Al @16K, Bh @32K, Bl @48K ; stage 64K ; 3 stages = 192K
#define TILE_B   16384
#define STAGE_B  65536
#define NSTAGE   3
#define SMEM_TOT (NSTAGE*STAGE_B)

// ---------------- split-bf16 mma.sync GEMM ------------------------------------
// C[m,n] = sum_k A[m,k]*B[n,k]  (NT), K=2048, all leading dims 2048.
// MODE 0: write split bf16 (Ch,Cl); 1: write fp32 Cf; 2: sum(relu(C)*w2s)->g_acc
template<int MODE>
__global__ void __launch_bounds__(256, 1) mma_gemm(
    const bf16* __restrict__ Ah, const bf16* __restrict__ Al,
    const bf16* __restrict__ Bh, const bf16* __restrict__ Bl,
    bf16* __restrict__ Ch, bf16* __restrict__ Cl, float* __restrict__ Cf,
    const float* __restrict__ w2s,
    size_t sA, size_t sB, size_t sC)
{
    extern __shared__ char smem[];
    const uint32_t sb = s2u(smem);

    const int tid = threadIdx.x;
    const int l   = tid & 31;
    const int wid = tid >> 5;
    const int wm  = wid & 1;          // 2 warps along M (64 rows each)
    const int wn  = wid >> 1;         // 4 warps along N (32 cols each)
    const int bn  = blockIdx.x * BN;
    const int bm  = blockIdx.y * BM;
    const size_t zo = blockIdx.z;

    Ah += zo * sA;  Al += zo * sA;
    Bh += zo * sB;  Bl += zo * sB;

    // ---- producer (cp.async) addressing: thread -> (row pr, 16B col pc)
    const int pr = tid >> 3;                 // 0..31
    const int pc = (tid & 7) * 16;           // byte col in 128B row
    const uint32_t pdst = (uint32_t)pr * 128u + ((uint32_t)pc ^ (((uint32_t)pr & 7u) << 4));
    const char* gAh = (const char*)(Ah + (size_t)(bm + pr) * KDIM) + pc;
    const char* gAl = (const char*)(Al + (size_t)(bm + pr) * KDIM) + pc;
    const char* gBh = (const char*)(Bh + (size_t)(bn + pr) * KDIM) + pc;
    const char* gBl = (const char*)(Bl + (size_t)(bn + pr) * KDIM) + pc;

    // ---- consumer (ldmatrix) addressing
    const int ar    = wm * 64 + (l & 15);        // A row (+ fm*16)
    const int akoff = (l >> 4) * 16;
    const uint32_t xA = ((uint32_t)ar & 7u) << 4;
    const int br    = wn * 32 + (l & 7) + ((l >> 4) & 1) * 8;   // B row (+ p*16)
    const int bkoff = ((l >> 3) & 1) * 16;
    const uint32_t xB = ((uint32_t)br & 7u) << 4;

    float acc[4][4][4];
    #pragma unroll
    for (int i = 0; i < 4; i++)
        #pragma unroll
        for (int j = 0; j < 4; j++)
            #pragma unroll
            for (int r = 0; r < 4; r++) acc[i][j][r] = 0.f;

    // ---- issue stages 0 and 1
    #pragma unroll
    for (int s = 0; s < 2; s++){
        const uint32_t s0 = sb + (uint32_t)s * STAGE_B;
        const size_t ko = (size_t)s * 128;
        #pragma unroll
        for (int j = 0; j < 4; j++){
            const size_t go = (size_t)j * 131072 + ko;   // +32 rows
            CPA(s0 +            pdst + j*4096, gAh + go);
            CPA(s0 + TILE_B   + pdst + j*4096, gAl + go);
            CPA(s0 + 2*TILE_B + pdst + j*4096, gBh + go);
            CPA(s0 + 3*TILE_B + pdst + j*4096, gBl + go);
        }
        CPA_COMMIT();
    }

    int bufc = 0;  // consume buffer
    int bufp = 2;  // produce buffer
    #pragma unroll 1
    for (int i = 0; i < KITERS; i++){
        if (i + 2 < KITERS){
            const uint32_t s0 = sb + (uint32_t)bufp * STAGE_B;
            const size_t ko = (size_t)(i + 2) * 128;
            #pragma unroll
            for (int j = 0; j < 4; j++){
                const size_t go = (size_t)j * 131072 + ko;
                CPA(s0 +            pdst + j*4096, gAh + go);
                CPA(s0 + TILE_B   + pdst + j*4096, gAl + go);
                CPA(s0 + 2*TILE_B + pdst + j*4096, gBh + go);
                CPA(s0 + 3*TILE_B + pdst + j*4096, gBl + go);
            }
            CPA_COMMIT();
            CPA_WAIT2();
        } else if (i + 1 < KITERS){
            CPA_WAIT1();
        } else {
            CPA_WAIT0();
        }
        __syncthreads();

        const uint32_t s0 = sb + (uint32_t)bufc * STAGE_B;
        #pragma unroll
        for (int ks = 0; ks < 4; ks++){
            const uint32_t kb = (uint32_t)ks * 32;
            uint32_t ah[4][4], al[4][4];
            #pragma unroll
            for (int fm = 0; fm < 4; fm++){
                uint32_t ad = s0 + (uint32_t)(ar + fm*16) * 128u + ((kb + akoff) ^ xA);
                ldm4(ah[fm], ad);
                ldm4(al[fm], ad + TILE_B);
            }
            uint32_t bh[2][4], bl[2][4];
            #pragma unroll
            for (int p = 0; p < 2; p++){
                uint32_t bd = s0 + 2*TILE_B + (uint32_t)(br + p*16) * 128u + ((kb + bkoff) ^ xB);
                ldm4(bh[p], bd);
                ldm4(bl[p], bd + TILE_B);
            }
            #pragma unroll
            for (int fm = 0; fm < 4; fm++)
                #pragma unroll
                for (int fn = 0; fn < 4; fn++){
                    const uint32_t* bhp = &bh[fn >> 1][(fn & 1) * 2];
                    const uint32_t* blp = &bl[fn >> 1][(fn & 1) * 2];
                    mma_bf16(acc[fm][fn], ah[fm], bhp);   // hi*hi
                    mma_bf16(acc[fm][fn], ah[fm], blp);   // hi*lo
                    mma_bf16(acc[fm][fn], al[fm], bhp);   // lo*hi
                }
        }
        __syncthreads();

        bufc = (bufc + 1 == NSTAGE) ? 0 : bufc + 1;
        bufp = (bufp + 1 == NSTAGE) ? 0 : bufp + 1;
    }

    // ---- epilogue
    const int crow = l >> 2;
    const int ccol = (l & 3) * 2;
    double local = 0.0;

    #pragma unroll
    for (int fm = 0; fm < 4; fm++){
        #pragma unroll
        for (int fn = 0; fn < 4; fn++){
            const int m0 = bm + wm*64 + fm*16 + crow;
            const int n0 = bn + wn*32 + fn*8 + ccol;
            const float* c = acc[fm][fn];
            if (MODE == 1){
                float* base = Cf + zo*sC;
                *(float2*)(base + (size_t)m0 * KDIM + n0)       = make_float2(c[0], c[1]);
                *(float2*)(base + (size_t)(m0+8) * KDIM + n0)   = make_float2(c[2], c[3]);
            } else if (MODE == 0){
                const size_t o0 = zo*sC + (size_t)m0 * KDIM + n0;
                const size_t o1 = zo*sC + (size_t)(m0+8) * KDIM + n0;
                #pragma unroll
                for (int h = 0; h < 2; h++){
                    float f0 = c[2*h], f1 = c[2*h+1];
                    bf16 h0 = __float2bfloat16_rn(f0);
                    bf16 h1 = __float2bfloat16_rn(f1);
                    bf16 l0 = __float2bfloat16_rn(f0 - __bfloat162float(h0));
                    bf16 l1 = __float2bfloat16_rn(f1 - __bfloat162float(h1));
                    size_t o = h ? o1 : o0;
                    *(uint32_t*)(Ch + o) = pk(h0, h1);
                    *(uint32_t*)(Cl + o) = pk(l0, l1);
                }
            } else {
                float w0 = w2s[n0], w1 = w2s[n0+1];
                float z;
                z = c[0]; local += (double)((z > 0.f ? z : 0.f) * w0);
                z = c[1]; local += (double)((z > 0.f ? z : 0.f) * w1);
                z = c[2]; local += (double)((z > 0.f ? z : 0.f) * w0);
                z = c[3]; local += (double)((z > 0.f ? z : 0.f) * w1);
            }
        }
    }

    if (MODE == 2){
        __syncthreads();
        double* red = (double*)smem;
        red[tid] = local;
        __syncthreads();
        #pragma unroll
        for (int s = 128; s > 0; s >>= 1){
            if (tid < s) red[tid] += red[tid + s];
            __syncthreads();
        }
        if (tid == 0) atomicAdd(&g_acc, red[0]);
    }
}

// ---------------- aux kernels -------------------------------------------------
__global__ void csplit_k(const float4* __restrict__ in, uint2* __restrict__ oh,
                         uint2* __restrict__ ol)
{
    size_t i = (size_t)blockIdx.x * 256 + threadIdx.x;
    float4 f = in[i];
    bf16 h0 = __float2bfloat16_rn(f.x), h1 = __float2bfloat16_rn(f.y);
    bf16 h2 = __float2bfloat16_rn(f.z), h3 = __float2bfloat16_rn(f.w);
    bf16 l0 = __float2bfloat16_rn(f.x - __bfloat162float(h0));
    bf16 l1 = __float2bfloat16_rn(f.y - __bfloat162float(h1));
    bf16 l2 = __float2bfloat16_rn(f.z - __bfloat162float(h2));
    bf16 l3 = __float2bfloat16_rn(f.w - __bfloat162float(h3));
    oh[i] = make_uint2(pk(h0,h1), pk(h2,h3));
    ol[i] = make_uint2(pk(l0,l1), pk(l2,l3));
}

// out[C][R] = in[R][C], split bf16 hi/lo; grid (C/32, R/32, z), block (32,8)
__global__ void tsplit_k(const float* __restrict__ in, bf16* __restrict__ oh,
                         bf16* __restrict__ ol, int R, int C, size_t sI, size_t sO)
{
    __shared__ float t[32][33];
    const float* src = in + (size_t)blockIdx.z * sI;
    int c0 = blockIdx.x * 32, r0 = blockIdx.y * 32;
    int tx = threadIdx.x, ty = threadIdx.y;
    #pragma unroll
    for (int j = 0; j < 32; j += 8)
        t[ty + j][tx] = src[(size_t)(r0 + ty + j) * C + c0 + tx];
    __syncthreads();
    #pragma unroll
    for (int j = 0; j < 32; j += 8){
        float f = t[tx][ty + j];
        bf16 h = __float2bfloat16_rn(f);
        bf16 lo = __float2bfloat16_rn(f - __bfloat162float(h));
        size_t o = (size_t)blockIdx.z * sO + (size_t)(c0 + ty + j) * R + r0 + tx;
        oh[o] = h;  ol[o] = lo;
    }
}

__global__ void softmax_k(const float* __restrict__ S, bf16* __restrict__ Ph,
                          bf16* __restrict__ Pl)
{
    const float* row = S + (size_t)blockIdx.x * SEQ;
    bf16* ph = Ph + (size_t)blockIdx.x * SEQ;
    bf16* pl = Pl + (size_t)blockIdx.x * SEQ;
    const int tid = threadIdx.x;  // 256
    __shared__ float sm[256];

    float v[8];
    float mx = -3.0e38f;
    #pragma unroll
    for (int t = 0; t < 8; t++){ v[t] = row[tid + 256*t]; mx = fmaxf(mx, v[t]); }
    sm[tid] = mx; __syncthreads();
    #pragma unroll
    for (int s = 128; s > 0; s >>= 1){
        if (tid < s) sm[tid] = fmaxf(sm[tid], sm[tid + s]);
        __syncthreads();
    }
    mx = sm[0]; __syncthreads();

    float sum = 0.f;
    #pragma unroll
    for (int t = 0; t < 8; t++){ v[t] = expf(v[t] - mx); sum += v[t]; }
    sm[tid] = sum; __syncthreads();
    #pragma unroll
    for (int s = 128; s > 0; s >>= 1){
        if (tid < s) sm[tid] += sm[tid + s];
        __syncthreads();
    }
    float inv = 1.0f / sm[0];
    #pragma unroll
    for (int t = 0; t < 8; t++){
        float f = v[t] * inv;
        bf16 h = __float2bfloat16_rn(f);
        bf16 lo = __float2bfloat16_rn(f - __bfloat162float(h));
        ph[tid + 256*t] = h;  pl[tid + 256*t] = lo;
    }
}

__global__ void w2sum_k(const float* __restrict__ W2)
{
    int e = blockIdx.x * 256 + threadIdx.x;
    if (e == 0) g_acc = 0.0;
    float s = 0.f;
    for (int d = 0; d < HD; d++) s += W2[(size_t)d * HD + e];
    g_w2s[e] = s;
}

__global__ void out_k(float* __restrict__ out){ out[0] = (float)g_acc; }

// ---------------- launch --------------------------------------------------------
extern "C" void kernel_launch(void* const* d_in, const int* in_sizes, int n_in,
                              void* d_out, int out_size)
{
    const float* x  = (const float*)d_in[0];
    const float* Wq = (const float*)d_in[1];
    const float* Wk = (const float*)d_in[2];
    const float* Wv = (const float*)d_in[3];
    const float* Wo = (const float*)d_in[4];
    const float* W1 = (const float*)d_in[5];
    const float* W2 = (const float*)d_in[6];

    cudaFuncSetAttribute(mma_gemm<0>, cudaFuncAttributeMaxDynamicSharedMemorySize, SMEM_TOT);
    cudaFuncSetAttribute(mma_gemm<1>, cudaFuncAttributeMaxDynamicSharedMemorySize, SMEM_TOT);
    cudaFuncSetAttribute(mma_gemm<2>, cudaFuncAttributeMaxDynamicSharedMemorySize, SMEM_TOT);

    bf16 *xh,*xl,*wqh,*wql,*wkh,*wkl,*wvh,*wvl,*w1h,*w1l,*woth,*wotl,*wfh,*wfl;
    bf16 *qh,*ql,*kh,*kl,*vth,*vtl,*ph,*pl,*ath,*atl;
    float *vf,*sc,*w2s;
    cudaGetSymbolAddress((void**)&xh, g_xh);   cudaGetSymbolAddress((void**)&xl, g_xl);
    cudaGetSymbolAddress((void**)&wqh, g_wqh); cudaGetSymbolAddress((void**)&wql, g_wql);
    cudaGetSymbolAddress((void**)&wkh, g_wkh); cudaGetSymbolAddress((void**)&wkl, g_wkl);
    cudaGetSymbolAddress((void**)&wvh, g_wvh); cudaGetSymbolAddress((void**)&wvl, g_wvl);
    cudaGetSymbolAddress((void**)&w1h, g_w1h); cudaGetSymbolAddress((void**)&w1l, g_w1l);
    cudaGetSymbolAddress((void**)&woth, g_woth); cudaGetSymbolAddress((void**)&wotl, g_wotl);
    cudaGetSymbolAddress((void**)&wfh, g_wfh); cudaGetSymbolAddress((void**)&wfl, g_wfl);
    cudaGetSymbolAddress((void**)&qh, g_qh);   cudaGetSymbolAddress((void**)&ql, g_ql);
    cudaGetSymbolAddress((void**)&kh, g_kh);   cudaGetSymbolAddress((void**)&kl, g_kl);
    cudaGetSymbolAddress((void**)&vth, g_vth); cudaGetSymbolAddress((void**)&vtl, g_vtl);
    cudaGetSymbolAddress((void**)&ph, g_ph);   cudaGetSymbolAddress((void**)&pl, g_pl);
    cudaGetSymbolAddress((void**)&ath, g_ath); cudaGetSymbolAddress((void**)&atl, g_atl);
    cudaGetSymbolAddress((void**)&vf, g_vf);
    cudaGetSymbolAddress((void**)&sc, g_sc);
    cudaGetSymbolAddress((void**)&w2s, g_w2s);

    const size_t SH = (size_t)SEQ * HD;
    const size_t SS = (size_t)SEQ * SEQ;
    dim3 t8(32, 8);

    w2sum_k<<<HD/256, 256>>>(W2);

    // split fp32 -> bf16 hi/lo
    csplit_k<<<(int)((size_t)TOK*HD/1024), 256>>>((const float4*)x,  (uint2*)xh,  (uint2*)xl);
    csplit_k<<<HD*HD/1024, 256>>>((const float4*)Wq, (uint2*)wqh, (uint2*)wql);
    csplit_k<<<HD*HD/1024, 256>>>((const float4*)Wk, (uint2*)wkh, (uint2*)wkl);
    csplit_k<<<HD*HD/1024, 256>>>((const float4*)Wv, (uint2*)wvh, (uint2*)wvl);
    csplit_k<<<HD*HD/1024, 256>>>((const float4*)W1, (uint2*)w1h, (uint2*)w1l);
    tsplit_k<<<dim3(HD/32, HD/32, 1), t8>>>(Wo, woth, wotl, HD, HD, 0, 0);

    // q = x Wq^T, k = x Wk^T (split out), v = x Wv^T (fp32 out)
    dim3 gTok(HD/BN, TOK/BM, 1);
    mma_gemm<0><<<gTok, 256, SMEM_TOT>>>(xh, xl, wqh, wql, qh, ql, nullptr, nullptr, 0,0,0);
    mma_gemm<0><<<gTok, 256, SMEM_TOT>>>(xh, xl, wkh, wkl, kh, kl, nullptr, nullptr, 0,0,0);
    mma_gemm<1><<<gTok, 256, SMEM_TOT>>>(xh, xl, wvh, wvl, nullptr, nullptr, vf, nullptr, 0,0,0);

    // Wf = W1 @ Wo  (NT against Wo^T)
    dim3 gW(HD/BN, HD/BM, 1);
    mma_gemm<0><<<gW, 256, SMEM_TOT>>>(w1h, w1l, woth, wotl, wfh, wfl, nullptr, nullptr, 0,0,0);

    // v^T per batch
    tsplit_k<<<dim3(HD/32, SEQ/32, NB), t8>>>(vf, vth, vtl, SEQ, HD, SH, SH);

    // scores = q k^T per batch (fp32 out)
    dim3 gSc(SEQ/BN, SEQ/BM, NB);
    mma_gemm<1><<<gSc, 256, SMEM_TOT>>>(qh, ql, kh, kl, nullptr, nullptr, sc, nullptr, SH, SH, SS);

    softmax_k<<<NB*SEQ, 256>>>(sc, ph, pl);

    // attn = P @ v  (NT against v^T), split out
    dim3 gAt(HD/BN, SEQ/BM, NB);
    mma_gemm<0><<<gAt, 256, SMEM_TOT>>>(ph, pl, vth, vtl, ath, atl, nullptr, nullptr, SS, SH, SH);

    // final: Z = attn Wf^T, reduce sum(relu(Z) * w2sum)
    dim3 gFin(HD/BN, TOK/BM, 1);
    mma_gemm<2><<<gFin, 256, SMEM_TOT>>>(ath, atl, wfh, wfl, nullptr, nullptr, nullptr, w2s, 0,0,0);

    out_k<<<1,1>>>((float*)d_out);
}

// round 6
// speedup vs baseline: 1.4044x; 1.2813x over previous
#include <cuda_runtime.h>
#include <cuda_bf16.h>
#include <cstdint>

#define HD   2048
#define SEQ  2048
#define NB   4
#define TOK  (NB*SEQ)
#define KDIM 2048
#define BM   128
#define BN   128
#define BK   64                 // bf16 elems = 128 bytes per row
#define KITERS (KDIM/BK)        // 32

typedef __nv_bfloat16 bf16;

// ---------------- static device scratch --------------------------------------
__device__ bf16  g_xh[(size_t)TOK*HD],   g_xl[(size_t)TOK*HD];
__device__ bf16  g_wqth[(size_t)HD*HD],  g_wqtl[(size_t)HD*HD];   // Wq^T split
__device__ bf16  g_wkth[(size_t)HD*HD],  g_wktl[(size_t)HD*HD];   // Wk^T split
__device__ bf16  g_wvth[(size_t)HD*HD],  g_wvtl[(size_t)HD*HD];   // Wv^T split
__device__ bf16  g_woh[(size_t)HD*HD],   g_wol[(size_t)HD*HD];    // Wo split
__device__ bf16  g_w1h[(size_t)HD*HD],   g_w1l[(size_t)HD*HD];    // W1 split
__device__ bf16  g_wqkth[(size_t)HD*HD], g_wqktl[(size_t)HD*HD];  // (Wq^T Wk)^T
__device__ bf16  g_m1th[(size_t)HD*HD],  g_m1tl[(size_t)HD*HD];   // (Wo Wv)^T
__device__ bf16  g_wvfh[(size_t)HD*HD],  g_wvfl[(size_t)HD*HD];   // W1 Wo Wv
__device__ bf16  g_th[(size_t)TOK*HD],   g_tl[(size_t)TOK*HD];    // t = x Wqk
__device__ bf16  g_uth[(size_t)TOK*HD],  g_utl[(size_t)TOK*HD];   // u^T per batch
__device__ float g_sc[(size_t)NB*SEQ*SEQ];
__device__ bf16  g_ph[(size_t)NB*SEQ*SEQ], g_pl[(size_t)NB*SEQ*SEQ];
__device__ float g_w2s[HD];
__device__ double g_acc;

// ---------------- helpers -----------------------------------------------------
__device__ __forceinline__ uint32_t s2u(const void* p){
    uint32_t a;
    asm("{ .reg .u64 t; cvta.to.shared.u64 t, %1; cvt.u32.u64 %0, t; }" : "=r"(a) : "l"(p));
    return a;
}
__device__ __forceinline__ uint32_t pk(bf16 a, bf16 b){
    __nv_bfloat162 t(a, b); return *reinterpret_cast<uint32_t*>(&t);
}

#define CPA(dst, src) asm volatile("cp.async.cg.shared.global [%0], [%1], 16;" \
    :: "r"(dst), "l"(src) : "memory")
#define CPA_COMMIT() asm volatile("cp.async.commit_group;" ::: "memory")
#define CPA_WAIT1()  asm volatile("cp.async.wait_group 1;" ::: "memory")

__device__ __forceinline__ void ldm4(uint32_t* r, uint32_t addr){
    asm volatile("ldmatrix.sync.aligned.m8n8.x4.shared.b16 {%0,%1,%2,%3}, [%4];"
        : "=r"(r[0]), "=r"(r[1]), "=r"(r[2]), "=r"(r[3]) : "r"(addr));
}
__device__ __forceinline__ void mma_bf16(float* d, const uint32_t* a, const uint32_t* b){
    asm volatile(
        "mma.sync.aligned.m16n8k16.row.col.f32.bf16.bf16.f32 "
        "{%0,%1,%2,%3}, {%4,%5,%6,%7}, {%8,%9}, {%0,%1,%2,%3};"
        : "+f"(d[0]), "+f"(d[1]), "+f"(d[2]), "+f"(d[3])
        : "r"(a[0]), "r"(a[1]), "r"(a[2]), "r"(a[3]), "r"(b[0]), "r"(b[1]));
}

// SMEM stage: Ah @0, Al @16K, Bh @32K, Bl @48K ; stage 64K ; 3 stages = 192K
#define TILE_B   16384
#define STAGE_B  65536
#define NSTAGE   3
#define SMEM_TOT (NSTAGE*STAGE_B)

// ---------------- split-bf16 mma.sync GEMM ------------------------------------
// C[m,n] = sum_k A[m,k]*B[n,k]  (NT), K=2048, all leading dims 2048.
// MODE 0: write split bf16 (Ch,Cl); 1: write fp32 Cf; 2: sum(relu(C)*w2s)->g_acc
template<int MODE>
__global__ void __launch_bounds__(256, 1) mma_gemm(
    const bf16* __restrict__ Ah, const bf16* __restrict__ Al,
    const bf16* __restrict__ Bh, const bf16* __restrict__ Bl,
    bf16* __restrict__ Ch, bf16* __restrict__ Cl, float* __restrict__ Cf,
    const float* __restrict__ w2s,
    size_t sA, size_t sB, size_t sC)
{
    extern __shared__ char smem[];
    const uint32_t sb = s2u(smem);

    const int tid = threadIdx.x;
    const int l   = tid & 31;
    const int wid = tid >> 5;
    const int wm  = wid & 1;          // 2 warps along M (64 rows each)
    const int wn  = wid >> 1;         // 4 warps along N (32 cols each)
    const int bn  = blockIdx.x * BN;
    const int bm  = blockIdx.y * BM;
    const size_t zo = blockIdx.z;

    Ah += zo * sA;  Al += zo * sA;
    Bh += zo * sB;  Bl += zo * sB;

    // ---- producer (cp.async) addressing
    const int pr = tid >> 3;                 // 0..31
    const int pc = (tid & 7) * 16;           // byte col in 128B row
    const uint32_t pdst = (uint32_t)pr * 128u + ((uint32_t)pc ^ (((uint32_t)pr & 7u) << 4));
    const char* gAh = (const char*)(Ah + (size_t)(bm + pr) * KDIM) + pc;
    const char* gAl = (const char*)(Al + (size_t)(bm + pr) * KDIM) + pc;
    const char* gBh = (const char*)(Bh + (size_t)(bn + pr) * KDIM) + pc;
    const char* gBl = (const char*)(Bl + (size_t)(bn + pr) * KDIM) + pc;

    // ---- consumer (ldmatrix) addressing
    const int ar    = wm * 64 + (l & 15);
    const int akoff = (l >> 4) * 16;
    const uint32_t xA = ((uint32_t)ar & 7u) << 4;
    const int br    = wn * 32 + (l & 7) + ((l >> 4) & 1) * 8;
    const int bkoff = ((l >> 3) & 1) * 16;
    const uint32_t xB = ((uint32_t)br & 7u) << 4;

    float acc[4][4][4];
    #pragma unroll
    for (int i = 0; i < 4; i++)
        #pragma unroll
        for (int j = 0; j < 4; j++)
            #pragma unroll
            for (int r = 0; r < 4; r++) acc[i][j][r] = 0.f;

    // ---- prologue: chunks 0,1 into bufs 0,1
    #pragma unroll
    for (int s = 0; s < 2; s++){
        const uint32_t s0 = sb + (uint32_t)s * STAGE_B;
        const size_t ko = (size_t)s * 128;
        #pragma unroll
        for (int j = 0; j < 4; j++){
            const size_t go = (size_t)j * 131072 + ko;
            CPA(s0 +            pdst + j*4096, gAh + go);
            CPA(s0 + TILE_B   + pdst + j*4096, gAl + go);
            CPA(s0 + 2*TILE_B + pdst + j*4096, gBh + go);
            CPA(s0 + 3*TILE_B + pdst + j*4096, gBl + go);
        }
        CPA_COMMIT();
    }

    int bufc = 0;  // consume buffer
    int bufp = 2;  // produce buffer
    #pragma unroll 1
    for (int i = 0; i < KITERS; i++){
        CPA_WAIT1();
        __syncthreads();

        // produce chunk i+2 into just-freed buffer (after sync => safe)
        if (i + 2 < KITERS){
            const uint32_t s0 = sb + (uint32_t)bufp * STAGE_B;
            const size_t ko = (size_t)(i + 2) * 128;
            #pragma unroll
            for (int j = 0; j < 4; j++){
                const size_t go = (size_t)j * 131072 + ko;
                CPA(s0 +            pdst + j*4096, gAh + go);
                CPA(s0 + TILE_B   + pdst + j*4096, gAl + go);
                CPA(s0 + 2*TILE_B + pdst + j*4096, gBh + go);
                CPA(s0 + 3*TILE_B + pdst + j*4096, gBl + go);
            }
        }
        CPA_COMMIT();   // always commit to keep group counting aligned

        const uint32_t s0 = sb + (uint32_t)bufc * STAGE_B;
        #pragma unroll
        for (int ks = 0; ks < 4; ks++){
            const uint32_t kb = (uint32_t)ks * 32;
            uint32_t ah[4][4], al[4][4];
            #pragma unroll
            for (int fm = 0; fm < 4; fm++){
                uint32_t ad = s0 + (uint32_t)(ar + fm*16) * 128u + ((kb + akoff) ^ xA);
                ldm4(ah[fm], ad);
                ldm4(al[fm], ad + TILE_B);
            }
            uint32_t bh[2][4], bl[2][4];
            #pragma unroll
            for (int p = 0; p < 2; p++){
                uint32_t bd = s0 + 2*TILE_B + (uint32_t)(br + p*16) * 128u + ((kb + bkoff) ^ xB);
                ldm4(bh[p], bd);
                ldm4(bl[p], bd + TILE_B);
            }
            #pragma unroll
            for (int fm = 0; fm < 4; fm++)
                #pragma unroll
                for (int fn = 0; fn < 4; fn++){
                    const uint32_t* bhp = &bh[fn >> 1][(fn & 1) * 2];
                    const uint32_t* blp = &bl[fn >> 1][(fn & 1) * 2];
                    mma_bf16(acc[fm][fn], ah[fm], bhp);   // hi*hi
                    mma_bf16(acc[fm][fn], ah[fm], blp);   // hi*lo
                    mma_bf16(acc[fm][fn], al[fm], bhp);   // lo*hi
                }
        }

        bufc = (bufc + 1 == NSTAGE) ? 0 : bufc + 1;
        bufp = (bufp + 1 == NSTAGE) ? 0 : bufp + 1;
    }

    // ---- epilogue
    const int crow = l >> 2;
    const int ccol = (l & 3) * 2;
    double local = 0.0;

    #pragma unroll
    for (int fm = 0; fm < 4; fm++){
        #pragma unroll
        for (int fn = 0; fn < 4; fn++){
            const int m0 = bm + wm*64 + fm*16 + crow;
            const int n0 = bn + wn*32 + fn*8 + ccol;
            const float* c = acc[fm][fn];
            if (MODE == 1){
                float* base = Cf + zo*sC;
                *(float2*)(base + (size_t)m0 * KDIM + n0)       = make_float2(c[0], c[1]);
                *(float2*)(base + (size_t)(m0+8) * KDIM + n0)   = make_float2(c[2], c[3]);
            } else if (MODE == 0){
                const size_t o0 = zo*sC + (size_t)m0 * KDIM + n0;
                const size_t o1 = zo*sC + (size_t)(m0+8) * KDIM + n0;
                #pragma unroll
                for (int h = 0; h < 2; h++){
                    float f0 = c[2*h], f1 = c[2*h+1];
                    bf16 h0 = __float2bfloat16_rn(f0);
                    bf16 h1 = __float2bfloat16_rn(f1);
                    bf16 l0 = __float2bfloat16_rn(f0 - __bfloat162float(h0));
                    bf16 l1 = __float2bfloat16_rn(f1 - __bfloat162float(h1));
                    size_t o = h ? o1 : o0;
                    *(uint32_t*)(Ch + o) = pk(h0, h1);
                    *(uint32_t*)(Cl + o) = pk(l0, l1);
                }
            } else {
                float w0 = w2s[n0], w1 = w2s[n0+1];
                float z;
                z = c[0]; local += (double)((z > 0.f ? z : 0.f) * w0);
                z = c[1]; local += (double)((z > 0.f ? z : 0.f) * w1);
                z = c[2]; local += (double)((z > 0.f ? z : 0.f) * w0);
                z = c[3]; local += (double)((z > 0.f ? z : 0.f) * w1);
            }
        }
    }

    if (MODE == 2){
        __syncthreads();
        double* red = (double*)smem;
        red[tid] = local;
        __syncthreads();
        #pragma unroll
        for (int s = 128; s > 0; s >>= 1){
            if (tid < s) red[tid] += red[tid + s];
            __syncthreads();
        }
        if (tid == 0) atomicAdd(&g_acc, red[0]);
    }
}

// ---------------- aux kernels -------------------------------------------------
__global__ void csplit_k(const float4* __restrict__ in, uint2* __restrict__ oh,
                         uint2* __restrict__ ol)
{
    size_t i = (size_t)blockIdx.x * 256 + threadIdx.x;
    float4 f = in[i];
    bf16 h0 = __float2bfloat16_rn(f.x), h1 = __float2bfloat16_rn(f.y);
    bf16 h2 = __float2bfloat16_rn(f.z), h3 = __float2bfloat16_rn(f.w);
    bf16 l0 = __float2bfloat16_rn(f.x - __bfloat162float(h0));
    bf16 l1 = __float2bfloat16_rn(f.y - __bfloat162float(h1));
    bf16 l2 = __float2bfloat16_rn(f.z - __bfloat162float(h2));
    bf16 l3 = __float2bfloat16_rn(f.w - __bfloat162float(h3));
    oh[i] = make_uint2(pk(h0,h1), pk(h2,h3));
    ol[i] = make_uint2(pk(l0,l1), pk(l2,l3));
}

// out[C][R] = in[R][C], split bf16 hi/lo; grid (C/32, R/32, z), block (32,8)
__global__ void tsplit_k(const float* __restrict__ in, bf16* __restrict__ oh,
                         bf16* __restrict__ ol, int R, int C, size_t sI, size_t sO)
{
    __shared__ float t[32][33];
    const float* src = in + (size_t)blockIdx.z * sI;
    int c0 = blockIdx.x * 32, r0 = blockIdx.y * 32;
    int tx = threadIdx.x, ty = threadIdx.y;
    #pragma unroll
    for (int j = 0; j < 32; j += 8)
        t[ty + j][tx] = src[(size_t)(r0 + ty + j) * C + c0 + tx];
    __syncthreads();
    #pragma unroll
    for (int j = 0; j < 32; j += 8){
        float f = t[tx][ty + j];
        bf16 h = __float2bfloat16_rn(f);
        bf16 lo = __float2bfloat16_rn(f - __bfloat162float(h));
        size_t o = (size_t)blockIdx.z * sO + (size_t)(c0 + ty + j) * R + r0 + tx;
        oh[o] = h;  ol[o] = lo;
    }
}

__global__ void softmax_k(const float* __restrict__ S, bf16* __restrict__ Ph,
                          bf16* __restrict__ Pl)
{
    const float* row = S + (size_t)blockIdx.x * SEQ;
    bf16* ph = Ph + (size_t)blockIdx.x * SEQ;
    bf16* pl = Pl + (size_t)blockIdx.x * SEQ;
    const int tid = threadIdx.x;  // 256
    __shared__ float sm[256];

    float v[8];
    float mx = -3.0e38f;
    #pragma unroll
    for (int t = 0; t < 8; t++){ v[t] = row[tid + 256*t]; mx = fmaxf(mx, v[t]); }
    sm[tid] = mx; __syncthreads();
    #pragma unroll
    for (int s = 128; s > 0; s >>= 1){
        if (tid < s) sm[tid] = fmaxf(sm[tid], sm[tid + s]);
        __syncthreads();
    }
    mx = sm[0]; __syncthreads();

    float sum = 0.f;
    #pragma unroll
    for (int t = 0; t < 8; t++){ v[t] = expf(v[t] - mx); sum += v[t]; }
    sm[tid] = sum; __syncthreads();
    #pragma unroll
    for (int s = 128; s > 0; s >>= 1){
        if (tid < s) sm[tid] += sm[tid + s];
        __syncthreads();
    }
    float inv = 1.0f / sm[0];
    #pragma unroll
    for (int t = 0; t < 8; t++){
        float f = v[t] * inv;
        bf16 h = __float2bfloat16_rn(f);
        bf16 lo = __float2bfloat16_rn(f - __bfloat162float(h));
        ph[tid + 256*t] = h;  pl[tid + 256*t] = lo;
    }
}

__global__ void w2sum_k(const float* __restrict__ W2)
{
    int e = blockIdx.x * 256 + threadIdx.x;
    if (e == 0) g_acc = 0.0;
    float s = 0.f;
    for (int d = 0; d < HD; d++) s += W2[(size_t)d * HD + e];
    g_w2s[e] = s;
}

__global__ void out_k(float* __restrict__ out){ out[0] = (float)g_acc; }

// ---------------- launch --------------------------------------------------------
extern "C" void kernel_launch(void* const* d_in, const int* in_sizes, int n_in,
                              void* d_out, int out_size)
{
    const float* x  = (const float*)d_in[0];
    const float* Wq = (const float*)d_in[1];
    const float* Wk = (const float*)d_in[2];
    const float* Wv = (const float*)d_in[3];
    const float* Wo = (const float*)d_in[4];
    const float* W1 = (const float*)d_in[5];
    const float* W2 = (const float*)d_in[6];

    cudaFuncSetAttribute(mma_gemm<0>, cudaFuncAttributeMaxDynamicSharedMemorySize, SMEM_TOT);
    cudaFuncSetAttribute(mma_gemm<1>, cudaFuncAttributeMaxDynamicSharedMemorySize, SMEM_TOT);
    cudaFuncSetAttribute(mma_gemm<2>, cudaFuncAttributeMaxDynamicSharedMemorySize, SMEM_TOT);

    bf16 *xh,*xl,*wqth,*wqtl,*wkth,*wktl,*wvth,*wvtl,*woh,*wol,*w1h,*w1l;
    bf16 *wqkth,*wqktl,*m1th,*m1tl,*wvfh,*wvfl,*th,*tl,*uth,*utl,*ph,*pl;
    float *sc,*w2s;
    cudaGetSymbolAddress((void**)&xh, g_xh);       cudaGetSymbolAddress((void**)&xl, g_xl);
    cudaGetSymbolAddress((void**)&wqth, g_wqth);   cudaGetSymbolAddress((void**)&wqtl, g_wqtl);
    cudaGetSymbolAddress((void**)&wkth, g_wkth);   cudaGetSymbolAddress((void**)&wktl, g_wktl);
    cudaGetSymbolAddress((void**)&wvth, g_wvth);   cudaGetSymbolAddress((void**)&wvtl, g_wvtl);
    cudaGetSymbolAddress((void**)&woh, g_woh);     cudaGetSymbolAddress((void**)&wol, g_wol);
    cudaGetSymbolAddress((void**)&w1h, g_w1h);     cudaGetSymbolAddress((void**)&w1l, g_w1l);
    cudaGetSymbolAddress((void**)&wqkth, g_wqkth); cudaGetSymbolAddress((void**)&wqktl, g_wqktl);
    cudaGetSymbolAddress((void**)&m1th, g_m1th);   cudaGetSymbolAddress((void**)&m1tl, g_m1tl);
    cudaGetSymbolAddress((void**)&wvfh, g_wvfh);   cudaGetSymbolAddress((void**)&wvfl, g_wvfl);
    cudaGetSymbolAddress((void**)&th, g_th);       cudaGetSymbolAddress((void**)&tl, g_tl);
    cudaGetSymbolAddress((void**)&uth, g_uth);     cudaGetSymbolAddress((void**)&utl, g_utl);
    cudaGetSymbolAddress((void**)&ph, g_ph);       cudaGetSymbolAddress((void**)&pl, g_pl);
    cudaGetSymbolAddress((void**)&sc, g_sc);
    cudaGetSymbolAddress((void**)&w2s, g_w2s);

    const size_t SH = (size_t)SEQ * HD;
    const size_t SS = (size_t)SEQ * SEQ;
    dim3 t8(32, 8);
    dim3 gW(HD/BN, HD/BM, 1);

    w2sum_k<<<HD/256, 256>>>(W2);

    // input splits
    csplit_k<<<(int)((size_t)TOK*HD/1024), 256>>>((const float4*)x,  (uint2*)xh, (uint2*)xl);
    csplit_k<<<HD*HD/1024, 256>>>((const float4*)Wo, (uint2*)woh, (uint2*)wol);
    csplit_k<<<HD*HD/1024, 256>>>((const float4*)W1, (uint2*)w1h, (uint2*)w1l);
    tsplit_k<<<dim3(HD/32, HD/32, 1), t8>>>(Wq, wqth, wqtl, HD, HD, 0, 0);
    tsplit_k<<<dim3(HD/32, HD/32, 1), t8>>>(Wk, wkth, wktl, HD, HD, 0, 0);
    tsplit_k<<<dim3(HD/32, HD/32, 1), t8>>>(Wv, wvth, wvtl, HD, HD, 0, 0);

    // -------- score path: score = x (Wq^T Wk) x^T --------
    // Wqkt[j,i] = sum_d Wk[d,j] Wq[d,i]  = NT(Wk^T, Wq^T)
    mma_gemm<0><<<gW, 256, SMEM_TOT>>>(wkth, wktl, wqth, wqtl, wqkth, wqktl, nullptr, nullptr, 0,0,0);
    // t = NT(x, Wqkt)  [TOK, HD]
    dim3 gT(HD/BN, TOK/BM, 1);
    mma_gemm<0><<<gT, 256, SMEM_TOT>>>(xh, xl, wqkth, wqktl, th, tl, nullptr, nullptr, 0,0,0);
    // score[b] = NT(t[b], x[b])  fp32
    dim3 gSc(SEQ/BN, SEQ/BM, NB);
    mma_gemm<1><<<gSc, 256, SMEM_TOT>>>(th, tl, xh, xl, nullptr, nullptr, sc, nullptr, SH, SH, SS);

    softmax_k<<<NB*SEQ, 256>>>(sc, ph, pl);

    // -------- value path: Z = P (x Wvf^T),  Wvf = W1 Wo Wv --------
    // M1t[d,h] = sum_g Wv[g,d] Wo[h,g] = NT(Wv^T, Wo)   ( = (Wo Wv)^T )
    mma_gemm<0><<<gW, 256, SMEM_TOT>>>(wvth, wvtl, woh, wol, m1th, m1tl, nullptr, nullptr, 0,0,0);
    // Wvf[e,d] = sum_h W1[e,h] M1t[d,h] = NT(W1, M1t)
    mma_gemm<0><<<gW, 256, SMEM_TOT>>>(w1h, w1l, m1th, m1tl, wvfh, wvfl, nullptr, nullptr, 0,0,0);
    // uT[b][e,s] = sum_d Wvf[e,d] x[b][s,d] = NT(Wvf, x[b])
    dim3 gU(SEQ/BN, HD/BM, NB);
    mma_gemm<0><<<gU, 256, SMEM_TOT>>>(wvfh, wvfl, xh, xl, uth, utl, nullptr, nullptr, 0, SH, SH);
    // Z[b] = NT(P[b], uT[b]) with relu * w2sum reduce
    dim3 gZ(HD/BN, SEQ/BM, NB);
    mma_gemm<2><<<gZ, 256, SMEM_TOT>>>(ph, pl, uth, utl, nullptr, nullptr, nullptr, w2s, SS, SH, 0);

    out_k<<<1,1>>>((float*)d_out);
}

// round 7
// speedup vs baseline: 1.8105x; 1.2891x over previous
#include <cuda_runtime.h>
#include <cuda_fp16.h>
#include <cstdint>

#define HD   2048
#define SEQ  2048
#define NB   4
#define TOK  (NB*SEQ)
#define KDIM 2048
#define BM   128
#define BN   128
#define BK   64                 // fp16 elems = 128 bytes per row
#define KITERS (KDIM/BK)        // 32

typedef __half h16;

// ---------------- static device scratch (fp16 splits, scaled domains) --------
__device__ h16  g_xh[(size_t)TOK*HD],   g_xl[(size_t)TOK*HD];     // s=0
__device__ h16  g_wqth[(size_t)HD*HD],  g_wqtl[(size_t)HD*HD];    // Wq^T  s=6
__device__ h16  g_wkth[(size_t)HD*HD],  g_wktl[(size_t)HD*HD];    // Wk^T  s=6
__device__ h16  g_wvth[(size_t)HD*HD],  g_wvtl[(size_t)HD*HD];    // Wv^T  s=6
__device__ h16  g_woh[(size_t)HD*HD],   g_wol[(size_t)HD*HD];     // Wo    s=6
__device__ h16  g_w1h[(size_t)HD*HD],   g_w1l[(size_t)HD*HD];     // W1    s=6
__device__ h16  g_wqkth[(size_t)HD*HD], g_wqktl[(size_t)HD*HD];   // (Wq^T Wk)^T s=6
__device__ h16  g_m1th[(size_t)HD*HD],  g_m1tl[(size_t)HD*HD];    // (Wo Wv)^T   s=6
__device__ h16  g_wvfh[(size_t)HD*HD];                            // W1WoWv s=7 (hi only)
__device__ h16  g_th[(size_t)TOK*HD];                             // t s=1 (hi only)
__device__ h16  g_uth[(size_t)TOK*HD],  g_utl[(size_t)TOK*HD];    // u^T s=2
__device__ float g_sc[(size_t)NB*SEQ*SEQ];
__device__ h16  g_ph[(size_t)NB*SEQ*SEQ];                         // P s=0 (hi only)
__device__ float g_w2s[HD];
__device__ double g_acc;

// ---------------- helpers -----------------------------------------------------
__device__ __forceinline__ uint32_t s2u(const void* p){
    uint32_t a;
    asm("{ .reg .u64 t; cvta.to.shared.u64 t, %1; cvt.u32.u64 %0, t; }" : "=r"(a) : "l"(p));
    return a;
}
__device__ __forceinline__ uint32_t pkh(h16 a, h16 b){
    __half2 t(a, b); return *reinterpret_cast<uint32_t*>(&t);
}

#define CPA(dst, src) asm volatile("cp.async.cg.shared.global [%0], [%1], 16;" \
    :: "r"(dst), "l"(src) : "memory")
#define CPA_COMMIT() asm volatile("cp.async.commit_group;" ::: "memory")

__device__ __forceinline__ void ldm4(uint32_t* r, uint32_t addr){
    asm volatile("ldmatrix.sync.aligned.m8n8.x4.shared.b16 {%0,%1,%2,%3}, [%4];"
        : "=r"(r[0]), "=r"(r[1]), "=r"(r[2]), "=r"(r[3]) : "r"(addr));
}
__device__ __forceinline__ void mma_f16(float* d, const uint32_t* a, const uint32_t* b){
    asm volatile(
        "mma.sync.aligned.m16n8k16.row.col.f32.f16.f16.f32 "
        "{%0,%1,%2,%3}, {%4,%5,%6,%7}, {%8,%9}, {%0,%1,%2,%3};"
        : "+f"(d[0]), "+f"(d[1]), "+f"(d[2]), "+f"(d[3])
        : "r"(a[0]), "r"(a[1]), "r"(a[2]), "r"(a[3]), "r"(b[0]), "r"(b[1]));
}

#define TILE_B   16384
#define SMEM_TOT 196608     // 3x64K (3-term) or 4x48K (2-term)

// ---------------- split-fp16 mma.sync GEMM ------------------------------------
// C[m,n] = oscale * sum_k A[m,k]*B[n,k]  (NT), K=2048, leading dims 2048.
// TERMS=3: ah*bh + ah*bl + al*bh ; TERMS=2: ah*bh + ah*bl (A hi-only)
// MODE 0: write fp16 (Ch, optional Cl); 1: fp32 Cf; 2: sum(relu(C)*w2s)->g_acc
template<int MODE, int TERMS>
__global__ void __launch_bounds__(256, 1) mma_gemm(
    const h16* __restrict__ Ah, const h16* __restrict__ Al,
    const h16* __restrict__ Bh, const h16* __restrict__ Bl,
    h16* __restrict__ Ch, h16* __restrict__ Cl, float* __restrict__ Cf,
    const float* __restrict__ w2s, float oscale,
    size_t sA, size_t sB, size_t sC)
{
    constexpr uint32_t STAGE  = (TERMS == 3) ? 65536u : 49152u;
    constexpr int      NST    = (TERMS == 3) ? 3 : 4;
    constexpr uint32_t BH_OFF = (TERMS == 3) ? 32768u : 16384u;

    extern __shared__ char smem[];
    const uint32_t sb = s2u(smem);

    const int tid = threadIdx.x;
    const int l   = tid & 31;
    const int wid = tid >> 5;
    const int wm  = wid & 1;          // 2 warps along M (64 rows each)
    const int wn  = wid >> 1;         // 4 warps along N (32 cols each)
    const int bn  = blockIdx.x * BN;
    const int bm  = blockIdx.y * BM;
    const size_t zo = blockIdx.z;

    Ah += zo * sA;  Bh += zo * sB;  Bl += zo * sB;
    if (TERMS == 3) Al += zo * sA;

    // ---- producer (cp.async) addressing
    const int pr = tid >> 3;                 // 0..31
    const int pc = (tid & 7) * 16;           // byte col in 128B row
    const uint32_t pdst = (uint32_t)pr * 128u + ((uint32_t)pc ^ (((uint32_t)pr & 7u) << 4));
    const char* gAh = (const char*)(Ah + (size_t)(bm + pr) * KDIM) + pc;
    const char* gAl = (TERMS == 3) ? (const char*)(Al + (size_t)(bm + pr) * KDIM) + pc : nullptr;
    const char* gBh = (const char*)(Bh + (size_t)(bn + pr) * KDIM) + pc;
    const char* gBl = (const char*)(Bl + (size_t)(bn + pr) * KDIM) + pc;

    // ---- consumer (ldmatrix) addressing
    const int ar    = wm * 64 + (l & 15);
    const int akoff = (l >> 4) * 16;
    const uint32_t xA = ((uint32_t)ar & 7u) << 4;
    const int br    = wn * 32 + (l & 7) + ((l >> 4) & 1) * 8;
    const int bkoff = ((l >> 3) & 1) * 16;
    const uint32_t xB = ((uint32_t)br & 7u) << 4;

    float acc[4][4][4];
    #pragma unroll
    for (int i = 0; i < 4; i++)
        #pragma unroll
        for (int j = 0; j < 4; j++)
            #pragma unroll
            for (int r = 0; r < 4; r++) acc[i][j][r] = 0.f;

    // ---- prologue: chunks 0..NST-2
    #pragma unroll
    for (int s = 0; s < NST - 1; s++){
        const uint32_t s0 = sb + (uint32_t)s * STAGE;
        const size_t ko = (size_t)s * 128;
        #pragma unroll
        for (int j = 0; j < 4; j++){
            const size_t go = (size_t)j * 131072 + ko;
            CPA(s0 + pdst + j*4096, gAh + go);
            if (TERMS == 3) CPA(s0 + TILE_B + pdst + j*4096, gAl + go);
            CPA(s0 + BH_OFF          + pdst + j*4096, gBh + go);
            CPA(s0 + BH_OFF + TILE_B + pdst + j*4096, gBl + go);
        }
        CPA_COMMIT();
    }

    int bufc = 0;
    int bufp = NST - 1;
    #pragma unroll 1
    for (int i = 0; i < KITERS; i++){
        if (TERMS == 3) asm volatile("cp.async.wait_group 1;" ::: "memory");
        else            asm volatile("cp.async.wait_group 2;" ::: "memory");
        __syncthreads();

        // produce chunk i+NST-1 into the just-freed buffer
        if (i + NST - 1 < KITERS){
            const uint32_t s0 = sb + (uint32_t)bufp * STAGE;
            const size_t ko = (size_t)(i + NST - 1) * 128;
            #pragma unroll
            for (int j = 0; j < 4; j++){
                const size_t go = (size_t)j * 131072 + ko;
                CPA(s0 + pdst + j*4096, gAh + go);
                if (TERMS == 3) CPA(s0 + TILE_B + pdst + j*4096, gAl + go);
                CPA(s0 + BH_OFF          + pdst + j*4096, gBh + go);
                CPA(s0 + BH_OFF + TILE_B + pdst + j*4096, gBl + go);
            }
        }
        CPA_COMMIT();   // always commit to keep group counting aligned

        const uint32_t s0 = sb + (uint32_t)bufc * STAGE;
        #pragma unroll
        for (int ks = 0; ks < 4; ks++){
            const uint32_t kb = (uint32_t)ks * 32;
            uint32_t ah[4][4], al[4][4];
            #pragma unroll
            for (int fm = 0; fm < 4; fm++){
                uint32_t ad = s0 + (uint32_t)(ar + fm*16) * 128u + ((kb + akoff) ^ xA);
                ldm4(ah[fm], ad);
                if (TERMS == 3) ldm4(al[fm], ad + TILE_B);
            }
            uint32_t bh[2][4], bl[2][4];
            #pragma unroll
            for (int p = 0; p < 2; p++){
                uint32_t bd = s0 + BH_OFF + (uint32_t)(br + p*16) * 128u + ((kb + bkoff) ^ xB);
                ldm4(bh[p], bd);
                ldm4(bl[p], bd + TILE_B);
            }
            #pragma unroll
            for (int fm = 0; fm < 4; fm++)
                #pragma unroll
                for (int fn = 0; fn < 4; fn++){
                    const uint32_t* bhp = &bh[fn >> 1][(fn & 1) * 2];
                    const uint32_t* blp = &bl[fn >> 1][(fn & 1) * 2];
                    mma_f16(acc[fm][fn], ah[fm], bhp);                  // hi*hi
                    mma_f16(acc[fm][fn], ah[fm], blp);                  // hi*lo
                    if (TERMS == 3) mma_f16(acc[fm][fn], al[fm], bhp);  // lo*hi
                }
        }

        bufc = (bufc + 1 == NST) ? 0 : bufc + 1;
        bufp = (bufp + 1 == NST) ? 0 : bufp + 1;
    }

    // ---- epilogue
    const int crow = l >> 2;
    const int ccol = (l & 3) * 2;
    const bool wlo = (Cl != nullptr);
    double local = 0.0;

    #pragma unroll
    for (int fm = 0; fm < 4; fm++){
        #pragma unroll
        for (int fn = 0; fn < 4; fn++){
            const int m0 = bm + wm*64 + fm*16 + crow;
            const int n0 = bn + wn*32 + fn*8 + ccol;
            const float* c = acc[fm][fn];
            if (MODE == 1){
                float* base = Cf + zo*sC;
                *(float2*)(base + (size_t)m0 * KDIM + n0)
                    = make_float2(c[0]*oscale, c[1]*oscale);
                *(float2*)(base + (size_t)(m0+8) * KDIM + n0)
                    = make_float2(c[2]*oscale, c[3]*oscale);
            } else if (MODE == 0){
                const size_t o0 = zo*sC + (size_t)m0 * KDIM + n0;
                const size_t o1 = zo*sC + (size_t)(m0+8) * KDIM + n0;
                #pragma unroll
                for (int h = 0; h < 2; h++){
                    float f0 = c[2*h] * oscale, f1 = c[2*h+1] * oscale;
                    h16 h0 = __float2half_rn(f0);
                    h16 h1 = __float2half_rn(f1);
                    size_t o = h ? o1 : o0;
                    *(uint32_t*)(Ch + o) = pkh(h0, h1);
                    if (wlo){
                        h16 l0 = __float2half_rn(f0 - __half2float(h0));
                        h16 l1 = __float2half_rn(f1 - __half2float(h1));
                        *(uint32_t*)(Cl + o) = pkh(l0, l1);
                    }
                }
            } else {
                float w0 = w2s[n0], w1 = w2s[n0+1];
                float z;
                z = c[0]*oscale; local += (double)((z > 0.f ? z : 0.f) * w0);
                z = c[1]*oscale; local += (double)((z > 0.f ? z : 0.f) * w1);
                z = c[2]*oscale; local += (double)((z > 0.f ? z : 0.f) * w0);
                z = c[3]*oscale; local += (double)((z > 0.f ? z : 0.f) * w1);
            }
        }
    }

    if (MODE == 2){
        __syncthreads();
        double* red = (double*)smem;
        red[tid] = local;
        __syncthreads();
        #pragma unroll
        for (int s = 128; s > 0; s >>= 1){
            if (tid < s) red[tid] += red[tid + s];
            __syncthreads();
        }
        if (tid == 0) atomicAdd(&g_acc, red[0]);
    }
}

// ---------------- aux kernels -------------------------------------------------
__global__ void csplit_k(const float4* __restrict__ in, uint2* __restrict__ oh,
                         uint2* __restrict__ ol, float scale)
{
    size_t i = (size_t)blockIdx.x * 256 + threadIdx.x;
    float4 f = in[i];
    f.x *= scale; f.y *= scale; f.z *= scale; f.w *= scale;
    h16 h0 = __float2half_rn(f.x), h1 = __float2half_rn(f.y);
    h16 h2 = __float2half_rn(f.z), h3 = __float2half_rn(f.w);
    h16 l0 = __float2half_rn(f.x - __half2float(h0));
    h16 l1 = __float2half_rn(f.y - __half2float(h1));
    h16 l2 = __float2half_rn(f.z - __half2float(h2));
    h16 l3 = __float2half_rn(f.w - __half2float(h3));
    oh[i] = make_uint2(pkh(h0,h1), pkh(h2,h3));
    ol[i] = make_uint2(pkh(l0,l1), pkh(l2,l3));
}

// out[C][R] = in[R][C] * scale, split fp16 hi/lo; grid (C/32, R/32, z), block (32,8)
__global__ void tsplit_k(const float* __restrict__ in, h16* __restrict__ oh,
                         h16* __restrict__ ol, int R, int C, float scale)
{
    __shared__ float t[32][33];
    int c0 = blockIdx.x * 32, r0 = blockIdx.y * 32;
    int tx = threadIdx.x, ty = threadIdx.y;
    #pragma unroll
    for (int j = 0; j < 32; j += 8)
        t[ty + j][tx] = in[(size_t)(r0 + ty + j) * C + c0 + tx];
    __syncthreads();
    #pragma unroll
    for (int j = 0; j < 32; j += 8){
        float f = t[tx][ty + j] * scale;
        h16 h = __float2half_rn(f);
        h16 lo = __float2half_rn(f - __half2float(h));
        size_t o = (size_t)(c0 + ty + j) * R + r0 + tx;
        oh[o] = h;  ol[o] = lo;
    }
}

__global__ void softmax_k(const float* __restrict__ S, h16* __restrict__ Ph)
{
    const float* row = S + (size_t)blockIdx.x * SEQ;
    h16* ph = Ph + (size_t)blockIdx.x * SEQ;
    const int tid = threadIdx.x;  // 256
    __shared__ float sm[256];

    float v[8];
    float mx = -3.0e38f;
    #pragma unroll
    for (int t = 0; t < 8; t++){ v[t] = row[tid + 256*t]; mx = fmaxf(mx, v[t]); }
    sm[tid] = mx; __syncthreads();
    #pragma unroll
    for (int s = 128; s > 0; s >>= 1){
        if (tid < s) sm[tid] = fmaxf(sm[tid], sm[tid + s]);
        __syncthreads();
    }
    mx = sm[0]; __syncthreads();

    float sum = 0.f;
    #pragma unroll
    for (int t = 0; t < 8; t++){ v[t] = expf(v[t] - mx); sum += v[t]; }
    sm[tid] = sum; __syncthreads();
    #pragma unroll
    for (int s = 128; s > 0; s >>= 1){
        if (tid < s) sm[tid] += sm[tid + s];
        __syncthreads();
    }
    float inv = 1.0f / sm[0];
    #pragma unroll
    for (int t = 0; t < 8; t++)
        ph[tid + 256*t] = __float2half_rn(v[t] * inv);
}

__global__ void w2sum_k(const float* __restrict__ W2)
{
    int e = blockIdx.x * 256 + threadIdx.x;
    if (e == 0) g_acc = 0.0;
    float s = 0.f;
    for (int d = 0; d < HD; d++) s += W2[(size_t)d * HD + e];
    g_w2s[e] = s;
}

__global__ void out_k(float* __restrict__ out){ out[0] = (float)g_acc; }

// ---------------- launch --------------------------------------------------------
extern "C" void kernel_launch(void* const* d_in, const int* in_sizes, int n_in,
                              void* d_out, int out_size)
{
    const float* x  = (const float*)d_in[0];
    const float* Wq = (const float*)d_in[1];
    const float* Wk = (const float*)d_in[2];
    const float* Wv = (const float*)d_in[3];
    const float* Wo = (const float*)d_in[4];
    const float* W1 = (const float*)d_in[5];
    const float* W2 = (const float*)d_in[6];

    cudaFuncSetAttribute(mma_gemm<0,3>, cudaFuncAttributeMaxDynamicSharedMemorySize, SMEM_TOT);
    cudaFuncSetAttribute(mma_gemm<0,2>, cudaFuncAttributeMaxDynamicSharedMemorySize, SMEM_TOT);
    cudaFuncSetAttribute(mma_gemm<1,2>, cudaFuncAttributeMaxDynamicSharedMemorySize, SMEM_TOT);
    cudaFuncSetAttribute(mma_gemm<2,2>, cudaFuncAttributeMaxDynamicSharedMemorySize, SMEM_TOT);

    h16 *xh,*xl,*wqth,*wqtl,*wkth,*wktl,*wvth,*wvtl,*woh,*wol,*w1h,*w1l;
    h16 *wqkth,*wqktl,*m1th,*m1tl,*wvfh,*th,*uth,*utl,*ph;
    float *sc,*w2s;
    cudaGetSymbolAddress((void**)&xh, g_xh);       cudaGetSymbolAddress((void**)&xl, g_xl);
    cudaGetSymbolAddress((void**)&wqth, g_wqth);   cudaGetSymbolAddress((void**)&wqtl, g_wqtl);
    cudaGetSymbolAddress((void**)&wkth, g_wkth);   cudaGetSymbolAddress((void**)&wktl, g_wktl);
    cudaGetSymbolAddress((void**)&wvth, g_wvth);   cudaGetSymbolAddress((void**)&wvtl, g_wvtl);
    cudaGetSymbolAddress((void**)&woh, g_woh);     cudaGetSymbolAddress((void**)&wol, g_wol);
    cudaGetSymbolAddress((void**)&w1h, g_w1h);     cudaGetSymbolAddress((void**)&w1l, g_w1l);
    cudaGetSymbolAddress((void**)&wqkth, g_wqkth); cudaGetSymbolAddress((void**)&wqktl, g_wqktl);
    cudaGetSymbolAddress((void**)&m1th, g_m1th);   cudaGetSymbolAddress((void**)&m1tl, g_m1tl);
    cudaGetSymbolAddress((void**)&wvfh, g_wvfh);
    cudaGetSymbolAddress((void**)&th, g_th);
    cudaGetSymbolAddress((void**)&uth, g_uth);     cudaGetSymbolAddress((void**)&utl, g_utl);
    cudaGetSymbolAddress((void**)&ph, g_ph);
    cudaGetSymbolAddress((void**)&sc, g_sc);
    cudaGetSymbolAddress((void**)&w2s, g_w2s);

    const size_t SH = (size_t)SEQ * HD;
    const size_t SS = (size_t)SEQ * SEQ;
    const float WS = 64.0f;           // weight pre-scale 2^6
    dim3 t8(32, 8);
    dim3 gW(HD/BN, HD/BM, 1);

    w2sum_k<<<HD/256, 256>>>(W2);

    // input splits (scaled)
    csplit_k<<<(int)((size_t)TOK*HD/1024), 256>>>((const float4*)x,  (uint2*)xh, (uint2*)xl, 1.0f);
    csplit_k<<<HD*HD/1024, 256>>>((const float4*)Wo, (uint2*)woh, (uint2*)wol, WS);
    csplit_k<<<HD*HD/1024, 256>>>((const float4*)W1, (uint2*)w1h, (uint2*)w1l, WS);
    tsplit_k<<<dim3(HD/32, HD/32, 1), t8>>>(Wq, wqth, wqtl, HD, HD, WS);
    tsplit_k<<<dim3(HD/32, HD/32, 1), t8>>>(Wk, wkth, wktl, HD, HD, WS);
    tsplit_k<<<dim3(HD/32, HD/32, 1), t8>>>(Wv, wvth, wvtl, HD, HD, WS);

    // -------- score path: score = x (Wq^T Wk) x^T --------
    // Wqkt[j,i] = sum_d Wk[d,j] Wq[d,i] = NT3(Wk^T, Wq^T); store s=6: os=2^(6-12)
    mma_gemm<0,3><<<gW, 256, SMEM_TOT>>>(wkth, wktl, wqth, wqtl, wqkth, wqktl,
                                         nullptr, nullptr, 0.015625f, 0,0,0);
    // t = NT2(x, Wqkt) hi-only; store s=1: os=2^(1-0-6)
    dim3 gT(HD/BN, TOK/BM, 1);
    mma_gemm<0,2><<<gT, 256, SMEM_TOT>>>(xh, nullptr, wqkth, wqktl, th, nullptr,
                                         nullptr, nullptr, 0.03125f, 0,0,0);
    // score[b] = NT2(t[b], x[b]) fp32; os=2^(0-1-0)
    dim3 gSc(SEQ/BN, SEQ/BM, NB);
    mma_gemm<1,2><<<gSc, 256, SMEM_TOT>>>(th, nullptr, xh, xl, nullptr, nullptr,
                                          sc, nullptr, 0.5f, SH, SH, SS);

    softmax_k<<<NB*SEQ, 256>>>(sc, ph);

    // -------- value path: Z = P (x Wvf^T), Wvf = W1 Wo Wv --------
    // M1t = NT3(Wv^T, Wo); store s=6: os=2^(6-12)
    mma_gemm<0,3><<<gW, 256, SMEM_TOT>>>(wvth, wvtl, woh, wol, m1th, m1tl,
                                         nullptr, nullptr, 0.015625f, 0,0,0);
    // Wvf = NT3(W1, M1t) hi-only; store s=7: os=2^(7-12)
    mma_gemm<0,3><<<gW, 256, SMEM_TOT>>>(w1h, w1l, m1th, m1tl, wvfh, nullptr,
                                         nullptr, nullptr, 0.03125f, 0,0,0);
    // uT[b] = NT2(Wvf, x[b]); store s=2: os=2^(2-7)
    dim3 gU(SEQ/BN, HD/BM, NB);
    mma_gemm<0,2><<<gU, 256, SMEM_TOT>>>(wvfh, nullptr, xh, xl, uth, utl,
                                         nullptr, nullptr, 0.03125f, 0, SH, SH);
    // Z[b] = NT2(P[b], uT[b]) reduce; os=2^(0-0-2)
    dim3 gZ(HD/BN, SEQ/BM, NB);
    mma_gemm<2,2><<<gZ, 256, SMEM_TOT>>>(ph, nullptr, uth, utl, nullptr, nullptr,
                                         nullptr, w2s, 0.25f, SS, SH, 0);

    out_k<<<1,1>>>((float*)d_out);
}

// round 8
// speedup vs baseline: 2.2816x; 1.2603x over previous
#include <cuda_runtime.h>
#include <cuda_fp16.h>
#include <cstdint>

#define HD   2048
#define SEQ  2048
#define NB   4
#define TOK  (NB*SEQ)
#define KDIM 2048
#define BM   128
#define BN   128
#define BK   64                 // fp16 elems = 128 bytes per row
#define KITERS (KDIM/BK)        // 32

typedef __half h16;

// ---------------- static device scratch (fp16 splits, scaled domains) --------
__device__ h16  g_xh[(size_t)TOK*HD];                             // x s=0 (hi only)
__device__ h16  g_wqth[(size_t)HD*HD],  g_wqtl[(size_t)HD*HD];    // Wq^T  s=6
__device__ h16  g_wkth[(size_t)HD*HD],  g_wktl[(size_t)HD*HD];    // Wk^T  s=6
__device__ h16  g_wvth[(size_t)HD*HD],  g_wvtl[(size_t)HD*HD];    // Wv^T  s=6
__device__ h16  g_woh[(size_t)HD*HD],   g_wol[(size_t)HD*HD];     // Wo    s=6
__device__ h16  g_w1h[(size_t)HD*HD],   g_w1l[(size_t)HD*HD];     // W1    s=6
__device__ h16  g_wqkth[(size_t)HD*HD], g_wqktl[(size_t)HD*HD];   // (Wq^T Wk)^T s=6
__device__ h16  g_m1th[(size_t)HD*HD],  g_m1tl[(size_t)HD*HD];    // (Wo Wv)^T   s=6
__device__ h16  g_wvfh[(size_t)HD*HD];                            // W1WoWv s=7 (hi only)
__device__ h16  g_th[(size_t)TOK*HD];                             // t s=1 (hi only)
__device__ h16  g_uth[(size_t)TOK*HD];                            // u^T s=2 (hi only)
__device__ float g_sc[(size_t)NB*SEQ*SEQ];
__device__ h16  g_ph[(size_t)NB*SEQ*SEQ];                         // P s=0 (hi only)
__device__ float g_w2s[HD];
__device__ double g_acc;

// ---------------- helpers -----------------------------------------------------
__device__ __forceinline__ uint32_t s2u(const void* p){
    uint32_t a;
    asm("{ .reg .u64 t; cvta.to.shared.u64 t, %1; cvt.u32.u64 %0, t; }" : "=r"(a) : "l"(p));
    return a;
}
__device__ __forceinline__ uint32_t pkh(h16 a, h16 b){
    __half2 t(a, b); return *reinterpret_cast<uint32_t*>(&t);
}

#define CPA(dst, src) asm volatile("cp.async.cg.shared.global [%0], [%1], 16;" \
    :: "r"(dst), "l"(src) : "memory")
#define CPA_COMMIT() asm volatile("cp.async.commit_group;" ::: "memory")

__device__ __forceinline__ void ldm4(uint32_t* r, uint32_t addr){
    asm volatile("ldmatrix.sync.aligned.m8n8.x4.shared.b16 {%0,%1,%2,%3}, [%4];"
        : "=r"(r[0]), "=r"(r[1]), "=r"(r[2]), "=r"(r[3]) : "r"(addr));
}
__device__ __forceinline__ void mma_f16(float* d, const uint32_t* a, const uint32_t* b){
    asm volatile(
        "mma.sync.aligned.m16n8k16.row.col.f32.f16.f16.f32 "
        "{%0,%1,%2,%3}, {%4,%5,%6,%7}, {%8,%9}, {%0,%1,%2,%3};"
        : "+f"(d[0]), "+f"(d[1]), "+f"(d[2]), "+f"(d[3])
        : "r"(a[0]), "r"(a[1]), "r"(a[2]), "r"(a[3]), "r"(b[0]), "r"(b[1]));
}

#define TILE_B   16384
#define SMEM_TOT 196608     // 3x64K (3t) / 4x48K (2t) / 6x32K (1t)

// ---------------- split-fp16 mma.sync GEMM ------------------------------------
// C[m,n] = oscale * sum_k A[m,k]*B[n,k]  (NT), K=2048, leading dims 2048.
// TERMS=3: ah*bh+ah*bl+al*bh ; TERMS=2: ah*bh+ah*bl ; TERMS=1: ah*bh
// MODE 0: write fp16 (Ch, optional Cl); 1: fp32 Cf; 2: sum(relu(C)*w2s)->g_acc
template<int MODE, int TERMS>
__global__ void __launch_bounds__(256, 1) mma_gemm(
    const h16* __restrict__ Ah, const h16* __restrict__ Al,
    const h16* __restrict__ Bh, const h16* __restrict__ Bl,
    h16* __restrict__ Ch, h16* __restrict__ Cl, float* __restrict__ Cf,
    const float* __restrict__ w2s, float oscale,
    size_t sA, size_t sB, size_t sC)
{
    constexpr uint32_t STAGE  = (TERMS == 3) ? 65536u : (TERMS == 2) ? 49152u : 32768u;
    constexpr int      NST    = (TERMS == 3) ? 3 : (TERMS == 2) ? 4 : 6;
    constexpr uint32_t BH_OFF = (TERMS == 3) ? 32768u : 16384u;

    extern __shared__ char smem[];
    const uint32_t sb = s2u(smem);

    const int tid = threadIdx.x;
    const int l   = tid & 31;
    const int wid = tid >> 5;
    const int wm  = wid & 1;          // 2 warps along M (64 rows each)
    const int wn  = wid >> 1;         // 4 warps along N (32 cols each)
    const int bn  = blockIdx.x * BN;
    const int bm  = blockIdx.y * BM;
    const size_t zo = blockIdx.z;

    Ah += zo * sA;  Bh += zo * sB;
    if (TERMS == 3) Al += zo * sA;
    if (TERMS >= 2) Bl += zo * sB;

    // ---- producer (cp.async) addressing
    const int pr = tid >> 3;                 // 0..31
    const int pc = (tid & 7) * 16;           // byte col in 128B row
    const uint32_t pdst = (uint32_t)pr * 128u + ((uint32_t)pc ^ (((uint32_t)pr & 7u) << 4));
    const char* gAh = (const char*)(Ah + (size_t)(bm + pr) * KDIM) + pc;
    const char* gAl = (TERMS == 3) ? (const char*)(Al + (size_t)(bm + pr) * KDIM) + pc : nullptr;
    const char* gBh = (const char*)(Bh + (size_t)(bn + pr) * KDIM) + pc;
    const char* gBl = (TERMS >= 2) ? (const char*)(Bl + (size_t)(bn + pr) * KDIM) + pc : nullptr;

    // ---- consumer (ldmatrix) addressing
    const int ar    = wm * 64 + (l & 15);
    const int akoff = (l >> 4) * 16;
    const uint32_t xA = ((uint32_t)ar & 7u) << 4;
    const int br    = wn * 32 + (l & 7) + ((l >> 4) & 1) * 8;
    const int bkoff = ((l >> 3) & 1) * 16;
    const uint32_t xB = ((uint32_t)br & 7u) << 4;

    float acc[4][4][4];
    #pragma unroll
    for (int i = 0; i < 4; i++)
        #pragma unroll
        for (int j = 0; j < 4; j++)
            #pragma unroll
            for (int r = 0; r < 4; r++) acc[i][j][r] = 0.f;

    // ---- prologue: chunks 0..NST-2
    #pragma unroll
    for (int s = 0; s < NST - 1; s++){
        const uint32_t s0 = sb + (uint32_t)s * STAGE;
        const size_t ko = (size_t)s * 128;
        #pragma unroll
        for (int j = 0; j < 4; j++){
            const size_t go = (size_t)j * 131072 + ko;
            CPA(s0 + pdst + j*4096, gAh + go);
            if (TERMS == 3) CPA(s0 + TILE_B + pdst + j*4096, gAl + go);
            CPA(s0 + BH_OFF + pdst + j*4096, gBh + go);
            if (TERMS >= 2) CPA(s0 + BH_OFF + TILE_B + pdst + j*4096, gBl + go);
        }
        CPA_COMMIT();
    }

    int bufc = 0;
    int bufp = NST - 1;
    #pragma unroll 1
    for (int i = 0; i < KITERS; i++){
        if (TERMS == 3)      asm volatile("cp.async.wait_group 1;" ::: "memory");
        else if (TERMS == 2) asm volatile("cp.async.wait_group 2;" ::: "memory");
        else                 asm volatile("cp.async.wait_group 4;" ::: "memory");
        __syncthreads();

        // produce chunk i+NST-1 into the just-freed buffer
        if (i + NST - 1 < KITERS){
            const uint32_t s0 = sb + (uint32_t)bufp * STAGE;
            const size_t ko = (size_t)(i + NST - 1) * 128;
            #pragma unroll
            for (int j = 0; j < 4; j++){
                const size_t go = (size_t)j * 131072 + ko;
                CPA(s0 + pdst + j*4096, gAh + go);
                if (TERMS == 3) CPA(s0 + TILE_B + pdst + j*4096, gAl + go);
                CPA(s0 + BH_OFF + pdst + j*4096, gBh + go);
                if (TERMS >= 2) CPA(s0 + BH_OFF + TILE_B + pdst + j*4096, gBl + go);
            }
        }
        CPA_COMMIT();   // always commit to keep group counting aligned

        const uint32_t s0 = sb + (uint32_t)bufc * STAGE;
        #pragma unroll
        for (int ks = 0; ks < 4; ks++){
            const uint32_t kb = (uint32_t)ks * 32;
            uint32_t ah[4][4], al[4][4];
            #pragma unroll
            for (int fm = 0; fm < 4; fm++){
                uint32_t ad = s0 + (uint32_t)(ar + fm*16) * 128u + ((kb + akoff) ^ xA);
                ldm4(ah[fm], ad);
                if (TERMS == 3) ldm4(al[fm], ad + TILE_B);
            }
            uint32_t bh[2][4], bl[2][4];
            #pragma unroll
            for (int p = 0; p < 2; p++){
                uint32_t bd = s0 + BH_OFF + (uint32_t)(br + p*16) * 128u + ((kb + bkoff) ^ xB);
                ldm4(bh[p], bd);
                if (TERMS >= 2) ldm4(bl[p], bd + TILE_B);
            }
            #pragma unroll
            for (int fm = 0; fm < 4; fm++)
                #pragma unroll
                for (int fn = 0; fn < 4; fn++){
                    const uint32_t* bhp = &bh[fn >> 1][(fn & 1) * 2];
                    const uint32_t* blp = &bl[fn >> 1][(fn & 1) * 2];
                    mma_f16(acc[fm][fn], ah[fm], bhp);                  // hi*hi
                    if (TERMS >= 2) mma_f16(acc[fm][fn], ah[fm], blp);  // hi*lo
                    if (TERMS == 3) mma_f16(acc[fm][fn], al[fm], bhp);  // lo*hi
                }
        }

        bufc = (bufc + 1 == NST) ? 0 : bufc + 1;
        bufp = (bufp + 1 == NST) ? 0 : bufp + 1;
    }

    // ---- epilogue
    const int crow = l >> 2;
    const int ccol = (l & 3) * 2;
    const bool wlo = (Cl != nullptr);
    double local = 0.0;

    #pragma unroll
    for (int fm = 0; fm < 4; fm++){
        #pragma unroll
        for (int fn = 0; fn < 4; fn++){
            const int m0 = bm + wm*64 + fm*16 + crow;
            const int n0 = bn + wn*32 + fn*8 + ccol;
            const float* c = acc[fm][fn];
            if (MODE == 1){
                float* base = Cf + zo*sC;
                *(float2*)(base + (size_t)m0 * KDIM + n0)
                    = make_float2(c[0]*oscale, c[1]*oscale);
                *(float2*)(base + (size_t)(m0+8) * KDIM + n0)
                    = make_float2(c[2]*oscale, c[3]*oscale);
            } else if (MODE == 0){
                const size_t o0 = zo*sC + (size_t)m0 * KDIM + n0;
                const size_t o1 = zo*sC + (size_t)(m0+8) * KDIM + n0;
                #pragma unroll
                for (int h = 0; h < 2; h++){
                    float f0 = c[2*h] * oscale, f1 = c[2*h+1] * oscale;
                    h16 h0 = __float2half_rn(f0);
                    h16 h1 = __float2half_rn(f1);
                    size_t o = h ? o1 : o0;
                    *(uint32_t*)(Ch + o) = pkh(h0, h1);
                    if (wlo){
                        h16 l0 = __float2half_rn(f0 - __half2float(h0));
                        h16 l1 = __float2half_rn(f1 - __half2float(h1));
                        *(uint32_t*)(Cl + o) = pkh(l0, l1);
                    }
                }
            } else {
                float w0 = w2s[n0], w1 = w2s[n0+1];
                float z;
                z = c[0]*oscale; local += (double)((z > 0.f ? z : 0.f) * w0);
                z = c[1]*oscale; local += (double)((z > 0.f ? z : 0.f) * w1);
                z = c[2]*oscale; local += (double)((z > 0.f ? z : 0.f) * w0);
                z = c[3]*oscale; local += (double)((z > 0.f ? z : 0.f) * w1);
            }
        }
    }

    if (MODE == 2){
        __syncthreads();
        double* red = (double*)smem;
        red[tid] = local;
        __syncthreads();
        #pragma unroll
        for (int s = 128; s > 0; s >>= 1){
            if (tid < s) red[tid] += red[tid + s];
            __syncthreads();
        }
        if (tid == 0) atomicAdd(&g_acc, red[0]);
    }
}

// ---------------- aux kernels -------------------------------------------------
__global__ void csplit_k(const float4* __restrict__ in, uint2* __restrict__ oh,
                         uint2* __restrict__ ol, float scale)
{
    size_t i = (size_t)blockIdx.x * 256 + threadIdx.x;
    float4 f = in[i];
    f.x *= scale; f.y *= scale; f.z *= scale; f.w *= scale;
    h16 h0 = __float2half_rn(f.x), h1 = __float2half_rn(f.y);
    h16 h2 = __float2half_rn(f.z), h3 = __float2half_rn(f.w);
    oh[i] = make_uint2(pkh(h0,h1), pkh(h2,h3));
    if (ol){
        h16 l0 = __float2half_rn(f.x - __half2float(h0));
        h16 l1 = __float2half_rn(f.y - __half2float(h1));
        h16 l2 = __float2half_rn(f.z - __half2float(h2));
        h16 l3 = __float2half_rn(f.w - __half2float(h3));
        ol[i] = make_uint2(pkh(l0,l1), pkh(l2,l3));
    }
}

// out[C][R] = in[R][C] * scale, split fp16 hi/lo; grid (C/32, R/32), block (32,8)
__global__ void tsplit_k(const float* __restrict__ in, h16* __restrict__ oh,
                         h16* __restrict__ ol, int R, int C, float scale)
{
    __shared__ float t[32][33];
    int c0 = blockIdx.x * 32, r0 = blockIdx.y * 32;
    int tx = threadIdx.x, ty = threadIdx.y;
    #pragma unroll
    for (int j = 0; j < 32; j += 8)
        t[ty + j][tx] = in[(size_t)(r0 + ty + j) * C + c0 + tx];
    __syncthreads();
    #pragma unroll
    for (int j = 0; j < 32; j += 8){
        float f = t[tx][ty + j] * scale;
        h16 h = __float2half_rn(f);
        h16 lo = __float2half_rn(f - __half2float(h));
        size_t o = (size_t)(c0 + ty + j) * R + r0 + tx;
        oh[o] = h;  ol[o] = lo;
    }
}

__global__ void softmax_k(const float* __restrict__ S, h16* __restrict__ Ph)
{
    const float* row = S + (size_t)blockIdx.x * SEQ;
    h16* ph = Ph + (size_t)blockIdx.x * SEQ;
    const int tid = threadIdx.x;  // 256
    __shared__ float sm[256];

    float v[8];
    float mx = -3.0e38f;
    #pragma unroll
    for (int t = 0; t < 8; t++){ v[t] = row[tid + 256*t]; mx = fmaxf(mx, v[t]); }
    sm[tid] = mx; __syncthreads();
    #pragma unroll
    for (int s = 128; s > 0; s >>= 1){
        if (tid < s) sm[tid] = fmaxf(sm[tid], sm[tid + s]);
        __syncthreads();
    }
    mx = sm[0]; __syncthreads();

    float sum = 0.f;
    #pragma unroll
    for (int t = 0; t < 8; t++){ v[t] = expf(v[t] - mx); sum += v[t]; }
    sm[tid] = sum; __syncthreads();
    #pragma unroll
    for (int s = 128; s > 0; s >>= 1){
        if (tid < s) sm[tid] += sm[tid + s];
        __syncthreads();
    }
    float inv = 1.0f / sm[0];
    #pragma unroll
    for (int t = 0; t < 8; t++)
        ph[tid + 256*t] = __float2half_rn(v[t] * inv);
}

__global__ void w2sum_k(const float* __restrict__ W2)
{
    int e = blockIdx.x * 256 + threadIdx.x;
    if (e == 0) g_acc = 0.0;
    float s = 0.f;
    for (int d = 0; d < HD; d++) s += W2[(size_t)d * HD + e];
    g_w2s[e] = s;
}

__global__ void out_k(float* __restrict__ out){ out[0] = (float)g_acc; }

// ---------------- launch --------------------------------------------------------
extern "C" void kernel_launch(void* const* d_in, const int* in_sizes, int n_in,
                              void* d_out, int out_size)
{
    const float* x  = (const float*)d_in[0];
    const float* Wq = (const float*)d_in[1];
    const float* Wk = (const float*)d_in[2];
    const float* Wv = (const float*)d_in[3];
    const float* Wo = (const float*)d_in[4];
    const float* W1 = (const float*)d_in[5];
    const float* W2 = (const float*)d_in[6];

    cudaFuncSetAttribute(mma_gemm<0,3>, cudaFuncAttributeMaxDynamicSharedMemorySize, SMEM_TOT);
    cudaFuncSetAttribute(mma_gemm<0,2>, cudaFuncAttributeMaxDynamicSharedMemorySize, SMEM_TOT);
    cudaFuncSetAttribute(mma_gemm<0,1>, cudaFuncAttributeMaxDynamicSharedMemorySize, SMEM_TOT);
    cudaFuncSetAttribute(mma_gemm<1,1>, cudaFuncAttributeMaxDynamicSharedMemorySize, SMEM_TOT);
    cudaFuncSetAttribute(mma_gemm<2,1>, cudaFuncAttributeMaxDynamicSharedMemorySize, SMEM_TOT);

    h16 *xh,*wqth,*wqtl,*wkth,*wktl,*wvth,*wvtl,*woh,*wol,*w1h,*w1l;
    h16 *wqkth,*wqktl,*m1th,*m1tl,*wvfh,*th,*uth,*ph;
    float *sc,*w2s;
    cudaGetSymbolAddress((void**)&xh, g_xh);
    cudaGetSymbolAddress((void**)&wqth, g_wqth);   cudaGetSymbolAddress((void**)&wqtl, g_wqtl);
    cudaGetSymbolAddress((void**)&wkth, g_wkth);   cudaGetSymbolAddress((void**)&wktl, g_wktl);
    cudaGetSymbolAddress((void**)&wvth, g_wvth);   cudaGetSymbolAddress((void**)&wvtl, g_wvtl);
    cudaGetSymbolAddress((void**)&woh, g_woh);     cudaGetSymbolAddress((void**)&wol, g_wol);
    cudaGetSymbolAddress((void**)&w1h, g_w1h);     cudaGetSymbolAddress((void**)&w1l, g_w1l);
    cudaGetSymbolAddress((void**)&wqkth, g_wqkth); cudaGetSymbolAddress((void**)&wqktl, g_wqktl);
    cudaGetSymbolAddress((void**)&m1th, g_m1th);   cudaGetSymbolAddress((void**)&m1tl, g_m1tl);
    cudaGetSymbolAddress((void**)&wvfh, g_wvfh);
    cudaGetSymbolAddress((void**)&th, g_th);
    cudaGetSymbolAddress((void**)&uth, g_uth);
    cudaGetSymbolAddress((void**)&ph, g_ph);
    cudaGetSymbolAddress((void**)&sc, g_sc);
    cudaGetSymbolAddress((void**)&w2s, g_w2s);

    const size_t SH = (size_t)SEQ * HD;
    const size_t SS = (size_t)SEQ * SEQ;
    const float WS = 64.0f;           // weight pre-scale 2^6
    dim3 t8(32, 8);
    dim3 gW(HD/BN, HD/BM, 1);

    w2sum_k<<<HD/256, 256>>>(W2);

    // input splits (scaled); x is hi-only
    csplit_k<<<(int)((size_t)TOK*HD/1024), 256>>>((const float4*)x,  (uint2*)xh, nullptr, 1.0f);
    csplit_k<<<HD*HD/1024, 256>>>((const float4*)Wo, (uint2*)woh, (uint2*)wol, WS);
    csplit_k<<<HD*HD/1024, 256>>>((const float4*)W1, (uint2*)w1h, (uint2*)w1l, WS);
    tsplit_k<<<dim3(HD/32, HD/32, 1), t8>>>(Wq, wqth, wqtl, HD, HD, WS);
    tsplit_k<<<dim3(HD/32, HD/32, 1), t8>>>(Wk, wkth, wktl, HD, HD, WS);
    tsplit_k<<<dim3(HD/32, HD/32, 1), t8>>>(Wv, wvth, wvtl, HD, HD, WS);

    // -------- score path: score = x (Wq^T Wk) x^T --------
    // Wqkt = NT3(Wk^T, Wq^T); store s=6: os=2^(6-12)
    mma_gemm<0,3><<<gW, 256, SMEM_TOT>>>(wkth, wktl, wqth, wqtl, wqkth, wqktl,
                                         nullptr, nullptr, 0.015625f, 0,0,0);
    // t = NT2(x, Wqkt) hi-only; store s=1: os=2^(1-0-6)
    dim3 gT(HD/BN, TOK/BM, 1);
    mma_gemm<0,2><<<gT, 256, SMEM_TOT>>>(xh, nullptr, wqkth, wqktl, th, nullptr,
                                         nullptr, nullptr, 0.03125f, 0,0,0);
    // score[b] = NT1(t[b], x[b]) fp32; os=2^(0-1-0)
    dim3 gSc(SEQ/BN, SEQ/BM, NB);
    mma_gemm<1,1><<<gSc, 256, SMEM_TOT>>>(th, nullptr, xh, nullptr, nullptr, nullptr,
                                          sc, nullptr, 0.5f, SH, SH, SS);

    softmax_k<<<NB*SEQ, 256>>>(sc, ph);

    // -------- value path: Z = P (x Wvf^T), Wvf = W1 Wo Wv --------
    // M1t = NT3(Wv^T, Wo); store s=6: os=2^(6-12)
    mma_gemm<0,3><<<gW, 256, SMEM_TOT>>>(wvth, wvtl, woh, wol, m1th, m1tl,
                                         nullptr, nullptr, 0.015625f, 0,0,0);
    // Wvf = NT3(W1, M1t) hi-only; store s=7: os=2^(7-12)
    mma_gemm<0,3><<<gW, 256, SMEM_TOT>>>(w1h, w1l, m1th, m1tl, wvfh, nullptr,
                                         nullptr, nullptr, 0.03125f, 0,0,0);
    // uT[b] = NT1(Wvf, x[b]) hi-only; store s=2: os=2^(2-7)
    dim3 gU(SEQ/BN, HD/BM, NB);
    mma_gemm<0,1><<<gU, 256, SMEM_TOT>>>(wvfh, nullptr, xh, nullptr, uth, nullptr,
                                         nullptr, nullptr, 0.03125f, 0, SH, SH);
    // Z[b] = NT1(P[b], uT[b]) reduce; os=2^(0-0-2)
    dim3 gZ(HD/BN, SEQ/BM, NB);
    mma_gemm<2,1><<<gZ, 256, SMEM_TOT>>>(ph, nullptr, uth, nullptr, nullptr, nullptr,
                                         nullptr, w2s, 0.25f, SS, SH, 0);

    out_k<<<1,1>>>((float*)d_out);
}

// round 9
// speedup vs baseline: 2.7478x; 1.2043x over previous
#include <cuda_runtime.h>
#include <cuda_fp16.h>
#include <cstdint>

#define HD   2048
#define SEQ  2048
#define NB   4
#define TOK  (NB*SEQ)
#define KDIM 2048
#define BM   128
#define BN   128
#define BK   64                 // fp16 elems = 128 bytes per row
#define KITERS (KDIM/BK)        // 32

typedef __half h16;

// ---------------- static device scratch (fp16, scaled domains) ----------------
__device__ h16  g_xh[(size_t)TOK*HD];                             // x s=0 (hi)
__device__ h16  g_wqth[(size_t)HD*HD],  g_wqtl[(size_t)HD*HD];    // Wq^T s=6 split
__device__ h16  g_wkth[(size_t)HD*HD];                            // Wk^T s=6 hi
__device__ h16  g_wvth[(size_t)HD*HD];                            // Wv^T s=6 hi
__device__ h16  g_woh[(size_t)HD*HD],   g_wol[(size_t)HD*HD];     // Wo   s=6 split
__device__ h16  g_w1h[(size_t)HD*HD];                             // W1   s=6 hi
__device__ h16  g_wqkth[(size_t)HD*HD];                           // (Wq^T Wk)^T s=6 hi
__device__ h16  g_m1th[(size_t)HD*HD],  g_m1tl[(size_t)HD*HD];    // (Wo Wv)^T s=6 split
__device__ h16  g_wvfh[(size_t)HD*HD];                            // W1WoWv s=7 hi
__device__ h16  g_th[(size_t)TOK*HD];                             // t s=1 hi
__device__ h16  g_uth[(size_t)TOK*HD];                            // u^T s=2 hi
__device__ float g_sc[(size_t)NB*SEQ*SEQ];
__device__ h16  g_ph[(size_t)NB*SEQ*SEQ];                         // P s=0 hi
__device__ float g_w2s[HD];
__device__ double g_acc;

// ---------------- helpers -----------------------------------------------------
__device__ __forceinline__ uint32_t s2u(const void* p){
    uint32_t a;
    asm("{ .reg .u64 t; cvta.to.shared.u64 t, %1; cvt.u32.u64 %0, t; }" : "=r"(a) : "l"(p));
    return a;
}
__device__ __forceinline__ uint32_t pkh(h16 a, h16 b){
    __half2 t(a, b); return *reinterpret_cast<uint32_t*>(&t);
}

#define CPA(dst, src) asm volatile("cp.async.cg.shared.global [%0], [%1], 16;" \
    :: "r"(dst), "l"(src) : "memory")
#define CPA_COMMIT() asm volatile("cp.async.commit_group;" ::: "memory")

__device__ __forceinline__ void ldm4(uint32_t* r, uint32_t addr){
    asm volatile("ldmatrix.sync.aligned.m8n8.x4.shared.b16 {%0,%1,%2,%3}, [%4];"
        : "=r"(r[0]), "=r"(r[1]), "=r"(r[2]), "=r"(r[3]) : "r"(addr));
}
__device__ __forceinline__ void mma_f16(float* d, const uint32_t* a, const uint32_t* b){
    asm volatile(
        "mma.sync.aligned.m16n8k16.row.col.f32.f16.f16.f32 "
        "{%0,%1,%2,%3}, {%4,%5,%6,%7}, {%8,%9}, {%0,%1,%2,%3};"
        : "+f"(d[0]), "+f"(d[1]), "+f"(d[2]), "+f"(d[3])
        : "r"(a[0]), "r"(a[1]), "r"(a[2]), "r"(a[3]), "r"(b[0]), "r"(b[1]));
}

#define TILE_B   16384
#define SMEM_TOT 196608     // 4x48K (2t) / 6x32K (1t)

// ---------------- split-fp16 mma.sync GEMM ------------------------------------
// C[m,n] = oscale * sum_k A[m,k]*B[n,k]  (NT), K=2048, leading dims 2048.
// TERMS=2: ah*bh+ah*bl (A hi, B split) ; TERMS=1: ah*bh
// MODE 0: write fp16 (Ch, optional Cl); 1: fp32 Cf; 2: sum(relu(C)*w2s)->g_acc
template<int MODE, int TERMS>
__global__ void __launch_bounds__(256, 1) mma_gemm(
    const h16* __restrict__ Ah,
    const h16* __restrict__ Bh, const h16* __restrict__ Bl,
    h16* __restrict__ Ch, h16* __restrict__ Cl, float* __restrict__ Cf,
    const float* __restrict__ w2s, float oscale,
    size_t sA, size_t sB, size_t sC)
{
    constexpr uint32_t STAGE  = (TERMS == 2) ? 49152u : 32768u;
    constexpr int      NST    = (TERMS == 2) ? 4 : 6;
    constexpr uint32_t BH_OFF = 16384u;

    extern __shared__ char smem[];
    const uint32_t sb = s2u(smem);

    const int tid = threadIdx.x;
    const int l   = tid & 31;
    const int wid = tid >> 5;
    const int wm  = wid & 1;          // 2 warps along M (64 rows each)
    const int wn  = wid >> 1;         // 4 warps along N (32 cols each)
    const int bn  = blockIdx.x * BN;
    const int bm  = blockIdx.y * BM;
    const size_t zo = blockIdx.z;

    Ah += zo * sA;  Bh += zo * sB;
    if (TERMS == 2) Bl += zo * sB;

    // ---- producer (cp.async) addressing
    const int pr = tid >> 3;                 // 0..31
    const int pc = (tid & 7) * 16;           // byte col in 128B row
    const uint32_t pdst = (uint32_t)pr * 128u + ((uint32_t)pc ^ (((uint32_t)pr & 7u) << 4));
    const char* gAh = (const char*)(Ah + (size_t)(bm + pr) * KDIM) + pc;
    const char* gBh = (const char*)(Bh + (size_t)(bn + pr) * KDIM) + pc;
    const char* gBl = (TERMS == 2) ? (const char*)(Bl + (size_t)(bn + pr) * KDIM) + pc : nullptr;

    // ---- consumer (ldmatrix) addressing
    const int ar    = wm * 64 + (l & 15);
    const int akoff = (l >> 4) * 16;
    const uint32_t xA = ((uint32_t)ar & 7u) << 4;
    const int br    = wn * 32 + (l & 7) + ((l >> 4) & 1) * 8;
    const int bkoff = ((l >> 3) & 1) * 16;
    const uint32_t xB = ((uint32_t)br & 7u) << 4;

    float acc[4][4][4];
    #pragma unroll
    for (int i = 0; i < 4; i++)
        #pragma unroll
        for (int j = 0; j < 4; j++)
            #pragma unroll
            for (int r = 0; r < 4; r++) acc[i][j][r] = 0.f;

    // ---- prologue: chunks 0..NST-2
    #pragma unroll
    for (int s = 0; s < NST - 1; s++){
        const uint32_t s0 = sb + (uint32_t)s * STAGE;
        const size_t ko = (size_t)s * 128;
        #pragma unroll
        for (int j = 0; j < 4; j++){
            const size_t go = (size_t)j * 131072 + ko;
            CPA(s0 + pdst + j*4096, gAh + go);
            CPA(s0 + BH_OFF + pdst + j*4096, gBh + go);
            if (TERMS == 2) CPA(s0 + BH_OFF + TILE_B + pdst + j*4096, gBl + go);
        }
        CPA_COMMIT();
    }

    int bufc = 0;
    int bufp = NST - 1;
    #pragma unroll 1
    for (int i = 0; i < KITERS; i++){
        if (TERMS == 2) asm volatile("cp.async.wait_group 2;" ::: "memory");
        else            asm volatile("cp.async.wait_group 4;" ::: "memory");
        __syncthreads();

        // produce chunk i+NST-1 into the just-freed buffer
        if (i + NST - 1 < KITERS){
            const uint32_t s0 = sb + (uint32_t)bufp * STAGE;
            const size_t ko = (size_t)(i + NST - 1) * 128;
            #pragma unroll
            for (int j = 0; j < 4; j++){
                const size_t go = (size_t)j * 131072 + ko;
                CPA(s0 + pdst + j*4096, gAh + go);
                CPA(s0 + BH_OFF + pdst + j*4096, gBh + go);
                if (TERMS == 2) CPA(s0 + BH_OFF + TILE_B + pdst + j*4096, gBl + go);
            }
        }
        CPA_COMMIT();   // always commit to keep group counting aligned

        const uint32_t s0 = sb + (uint32_t)bufc * STAGE;
        #pragma unroll
        for (int ks = 0; ks < 4; ks++){
            const uint32_t kb = (uint32_t)ks * 32;
            uint32_t ah[4][4];
            #pragma unroll
            for (int fm = 0; fm < 4; fm++){
                uint32_t ad = s0 + (uint32_t)(ar + fm*16) * 128u + ((kb + akoff) ^ xA);
                ldm4(ah[fm], ad);
            }
            uint32_t bh[2][4], bl[2][4];
            #pragma unroll
            for (int p = 0; p < 2; p++){
                uint32_t bd = s0 + BH_OFF + (uint32_t)(br + p*16) * 128u + ((kb + bkoff) ^ xB);
                ldm4(bh[p], bd);
                if (TERMS == 2) ldm4(bl[p], bd + TILE_B);
            }
            #pragma unroll
            for (int fm = 0; fm < 4; fm++)
                #pragma unroll
                for (int fn = 0; fn < 4; fn++){
                    const uint32_t* bhp = &bh[fn >> 1][(fn & 1) * 2];
                    const uint32_t* blp = &bl[fn >> 1][(fn & 1) * 2];
                    mma_f16(acc[fm][fn], ah[fm], bhp);                  // hi*hi
                    if (TERMS == 2) mma_f16(acc[fm][fn], ah[fm], blp);  // hi*lo
                }
        }

        bufc = (bufc + 1 == NST) ? 0 : bufc + 1;
        bufp = (bufp + 1 == NST) ? 0 : bufp + 1;
    }

    // ---- epilogue
    const int crow = l >> 2;
    const int ccol = (l & 3) * 2;
    const bool wlo = (Cl != nullptr);
    double local = 0.0;

    #pragma unroll
    for (int fm = 0; fm < 4; fm++){
        #pragma unroll
        for (int fn = 0; fn < 4; fn++){
            const int m0 = bm + wm*64 + fm*16 + crow;
            const int n0 = bn + wn*32 + fn*8 + ccol;
            const float* c = acc[fm][fn];
            if (MODE == 1){
                float* base = Cf + zo*sC;
                *(float2*)(base + (size_t)m0 * KDIM + n0)
                    = make_float2(c[0]*oscale, c[1]*oscale);
                *(float2*)(base + (size_t)(m0+8) * KDIM + n0)
                    = make_float2(c[2]*oscale, c[3]*oscale);
            } else if (MODE == 0){
                const size_t o0 = zo*sC + (size_t)m0 * KDIM + n0;
                const size_t o1 = zo*sC + (size_t)(m0+8) * KDIM + n0;
                #pragma unroll
                for (int h = 0; h < 2; h++){
                    float f0 = c[2*h] * oscale, f1 = c[2*h+1] * oscale;
                    h16 h0 = __float2half_rn(f0);
                    h16 h1 = __float2half_rn(f1);
                    size_t o = h ? o1 : o0;
                    *(uint32_t*)(Ch + o) = pkh(h0, h1);
                    if (wlo){
                        h16 l0 = __float2half_rn(f0 - __half2float(h0));
                        h16 l1 = __float2half_rn(f1 - __half2float(h1));
                        *(uint32_t*)(Cl + o) = pkh(l0, l1);
                    }
                }
            } else {
                float w0 = w2s[n0], w1 = w2s[n0+1];
                float z;
                z = c[0]*oscale; local += (double)((z > 0.f ? z : 0.f) * w0);
                z = c[1]*oscale; local += (double)((z > 0.f ? z : 0.f) * w1);
                z = c[2]*oscale; local += (double)((z > 0.f ? z : 0.f) * w0);
                z = c[3]*oscale; local += (double)((z > 0.f ? z : 0.f) * w1);
            }
        }
    }

    if (MODE == 2){
        __syncthreads();
        double* red = (double*)smem;
        red[tid] = local;
        __syncthreads();
        #pragma unroll
        for (int s = 128; s > 0; s >>= 1){
            if (tid < s) red[tid] += red[tid + s];
            __syncthreads();
        }
        if (tid == 0) atomicAdd(&g_acc, red[0]);
    }
}

// ---------------- aux kernels -------------------------------------------------
__global__ void csplit_k(const float4* __restrict__ in, uint2* __restrict__ oh,
                         uint2* __restrict__ ol, float scale)
{
    size_t i = (size_t)blockIdx.x * 256 + threadIdx.x;
    float4 f = in[i];
    f.x *= scale; f.y *= scale; f.z *= scale; f.w *= scale;
    h16 h0 = __float2half_rn(f.x), h1 = __float2half_rn(f.y);
    h16 h2 = __float2half_rn(f.z), h3 = __float2half_rn(f.w);
    oh[i] = make_uint2(pkh(h0,h1), pkh(h2,h3));
    if (ol){
        h16 l0 = __float2half_rn(f.x - __half2float(h0));
        h16 l1 = __float2half_rn(f.y - __half2float(h1));
        h16 l2 = __float2half_rn(f.z - __half2float(h2));
        h16 l3 = __float2half_rn(f.w - __half2float(h3));
        ol[i] = make_uint2(pkh(l0,l1), pkh(l2,l3));
    }
}

// out[C][R] = in[R][C] * scale, fp16 hi (+ optional lo); grid (C/32, R/32), block (32,8)
__global__ void tsplit_k(const float* __restrict__ in, h16* __restrict__ oh,
                         h16* __restrict__ ol, int R, int C, float scale)
{
    __shared__ float t[32][33];
    int c0 = blockIdx.x * 32, r0 = blockIdx.y * 32;
    int tx = threadIdx.x, ty = threadIdx.y;
    #pragma unroll
    for (int j = 0; j < 32; j += 8)
        t[ty + j][tx] = in[(size_t)(r0 + ty + j) * C + c0 + tx];
    __syncthreads();
    #pragma unroll
    for (int j = 0; j < 32; j += 8){
        float f = t[tx][ty + j] * scale;
        h16 h = __float2half_rn(f);
        size_t o = (size_t)(c0 + ty + j) * R + r0 + tx;
        oh[o] = h;
        if (ol) ol[o] = __float2half_rn(f - __half2float(h));
    }
}

__global__ void softmax_k(const float* __restrict__ S, h16* __restrict__ Ph)
{
    const float* row = S + (size_t)blockIdx.x * SEQ;
    h16* ph = Ph + (size_t)blockIdx.x * SEQ;
    const int tid = threadIdx.x;  // 256
    __shared__ float sm[256];

    float v[8];
    float mx = -3.0e38f;
    #pragma unroll
    for (int t = 0; t < 8; t++){ v[t] = row[tid + 256*t]; mx = fmaxf(mx, v[t]); }
    sm[tid] = mx; __syncthreads();
    #pragma unroll
    for (int s = 128; s > 0; s >>= 1){
        if (tid < s) sm[tid] = fmaxf(sm[tid], sm[tid + s]);
        __syncthreads();
    }
    mx = sm[0]; __syncthreads();

    float sum = 0.f;
    #pragma unroll
    for (int t = 0; t < 8; t++){ v[t] = expf(v[t] - mx); sum += v[t]; }
    sm[tid] = sum; __syncthreads();
    #pragma unroll
    for (int s = 128; s > 0; s >>= 1){
        if (tid < s) sm[tid] += sm[tid + s];
        __syncthreads();
    }
    float inv = 1.0f / sm[0];
    #pragma unroll
    for (int t = 0; t < 8; t++)
        ph[tid + 256*t] = __float2half_rn(v[t] * inv);
}

__global__ void w2sum_k(const float* __restrict__ W2)
{
    int e = blockIdx.x * 256 + threadIdx.x;
    if (e == 0) g_acc = 0.0;
    float s = 0.f;
    for (int d = 0; d < HD; d++) s += W2[(size_t)d * HD + e];
    g_w2s[e] = s;
}

__global__ void out_k(float* __restrict__ out){ out[0] = (float)g_acc; }

// ---------------- launch --------------------------------------------------------
extern "C" void kernel_launch(void* const* d_in, const int* in_sizes, int n_in,
                              void* d_out, int out_size)
{
    const float* x  = (const float*)d_in[0];
    const float* Wq = (const float*)d_in[1];
    const float* Wk = (const float*)d_in[2];
    const float* Wv = (const float*)d_in[3];
    const float* Wo = (const float*)d_in[4];
    const float* W1 = (const float*)d_in[5];
    const float* W2 = (const float*)d_in[6];

    cudaFuncSetAttribute(mma_gemm<0,2>, cudaFuncAttributeMaxDynamicSharedMemorySize, SMEM_TOT);
    cudaFuncSetAttribute(mma_gemm<0,1>, cudaFuncAttributeMaxDynamicSharedMemorySize, SMEM_TOT);
    cudaFuncSetAttribute(mma_gemm<1,1>, cudaFuncAttributeMaxDynamicSharedMemorySize, SMEM_TOT);
    cudaFuncSetAttribute(mma_gemm<2,1>, cudaFuncAttributeMaxDynamicSharedMemorySize, SMEM_TOT);

    h16 *xh,*wqth,*wqtl,*wkth,*wvth,*woh,*wol,*w1h;
    h16 *wqkth,*m1th,*m1tl,*wvfh,*th,*uth,*ph;
    float *sc,*w2s;
    cudaGetSymbolAddress((void**)&xh, g_xh);
    cudaGetSymbolAddress((void**)&wqth, g_wqth);   cudaGetSymbolAddress((void**)&wqtl, g_wqtl);
    cudaGetSymbolAddress((void**)&wkth, g_wkth);
    cudaGetSymbolAddress((void**)&wvth, g_wvth);
    cudaGetSymbolAddress((void**)&woh, g_woh);     cudaGetSymbolAddress((void**)&wol, g_wol);
    cudaGetSymbolAddress((void**)&w1h, g_w1h);
    cudaGetSymbolAddress((void**)&wqkth, g_wqkth);
    cudaGetSymbolAddress((void**)&m1th, g_m1th);   cudaGetSymbolAddress((void**)&m1tl, g_m1tl);
    cudaGetSymbolAddress((void**)&wvfh, g_wvfh);
    cudaGetSymbolAddress((void**)&th, g_th);
    cudaGetSymbolAddress((void**)&uth, g_uth);
    cudaGetSymbolAddress((void**)&ph, g_ph);
    cudaGetSymbolAddress((void**)&sc, g_sc);
    cudaGetSymbolAddress((void**)&w2s, g_w2s);

    const size_t SH = (size_t)SEQ * HD;
    const size_t SS = (size_t)SEQ * SEQ;
    const float WS = 64.0f;           // weight pre-scale 2^6
    dim3 t8(32, 8);
    dim3 gW(HD/BN, HD/BM, 1);

    w2sum_k<<<HD/256, 256>>>(W2);

    // input splits (scaled)
    csplit_k<<<(int)((size_t)TOK*HD/1024), 256>>>((const float4*)x,  (uint2*)xh, nullptr, 1.0f);
    csplit_k<<<HD*HD/1024, 256>>>((const float4*)Wo, (uint2*)woh, (uint2*)wol, WS);
    csplit_k<<<HD*HD/1024, 256>>>((const float4*)W1, (uint2*)w1h, nullptr, WS);
    tsplit_k<<<dim3(HD/32, HD/32, 1), t8>>>(Wq, wqth, wqtl, HD, HD, WS);
    tsplit_k<<<dim3(HD/32, HD/32, 1), t8>>>(Wk, wkth, nullptr, HD, HD, WS);
    tsplit_k<<<dim3(HD/32, HD/32, 1), t8>>>(Wv, wvth, nullptr, HD, HD, WS);

    // -------- score path: score = x (Wq^T Wk) x^T --------
    // Wqkt = NT2(Wk^T hi, Wq^T split) hi-only; store s=6: os=2^(6-12)
    mma_gemm<0,2><<<gW, 256, SMEM_TOT>>>(wkth, wqth, wqtl, wqkth, nullptr,
                                         nullptr, nullptr, 0.015625f, 0,0,0);
    // t = NT1(x, Wqkt) hi-only; store s=1: os=2^(1-0-6)
    dim3 gT(HD/BN, TOK/BM, 1);
    mma_gemm<0,1><<<gT, 256, SMEM_TOT>>>(xh, wqkth, nullptr, th, nullptr,
                                         nullptr, nullptr, 0.03125f, 0,0,0);
    // score[b] = NT1(t[b], x[b]) fp32; os=2^(0-1-0)
    dim3 gSc(SEQ/BN, SEQ/BM, NB);
    mma_gemm<1,1><<<gSc, 256, SMEM_TOT>>>(th, xh, nullptr, nullptr, nullptr,
                                          sc, nullptr, 0.5f, SH, SH, SS);

    softmax_k<<<NB*SEQ, 256>>>(sc, ph);

    // -------- value path: Z = P (x Wvf^T), Wvf = W1 Wo Wv --------
    // M1t = NT2(Wv^T hi, Wo split) split out; store s=6: os=2^(6-12)
    mma_gemm<0,2><<<gW, 256, SMEM_TOT>>>(wvth, woh, wol, m1th, m1tl,
                                         nullptr, nullptr, 0.015625f, 0,0,0);
    // Wvf = NT2(W1 hi, M1t split) hi-only; store s=7: os=2^(7-12)
    mma_gemm<0,2><<<gW, 256, SMEM_TOT>>>(w1h, m1th, m1tl, wvfh, nullptr,
                                         nullptr, nullptr, 0.03125f, 0,0,0);
    // uT[b] = NT1(Wvf, x[b]) hi-only; store s=2: os=2^(2-7)
    dim3 gU(SEQ/BN, HD/BM, NB);
    mma_gemm<0,1><<<gU, 256, SMEM_TOT>>>(wvfh, xh, nullptr, uth, nullptr,
                                         nullptr, nullptr, 0.03125f, 0, SH, SH);
    // Z[b] = NT1(P[b], uT[b]) reduce; os=2^(0-0-2)
    dim3 gZ(HD/BN, SEQ/BM, NB);
    mma_gemm<2,1><<<gZ, 256, SMEM_TOT>>>(ph, uth, nullptr, nullptr, nullptr,
                                         nullptr, w2s, 0.25f, SS, SH, 0);

    out_k<<<1,1>>>((float*)d_out);
}

// round 10
// speedup vs baseline: 3.6626x; 1.3329x over previous
#include <cuda_runtime.h>
#include <cuda_fp16.h>
#include <cstdint>

#define HD   2048
#define SEQ  2048
#define NB   4
#define TOK  (NB*SEQ)
#define KDIM 2048
#define BM   128
#define BN   128
#define BK   64                 // fp16 elems = 128 bytes per row
#define KITERS (KDIM/BK)        // 32

typedef __half h16;

// ---------------- static device scratch (fp16 hi-only, scaled domains) --------
__device__ h16  g_xh[(size_t)TOK*HD];                             // x    s=0
__device__ h16  g_wqth[(size_t)HD*HD];                            // Wq^T s=6
__device__ h16  g_wkth[(size_t)HD*HD];                            // Wk^T s=6
__device__ h16  g_wvth[(size_t)HD*HD];                            // Wv^T s=6
__device__ h16  g_woh[(size_t)HD*HD];                             // Wo   s=6
__device__ h16  g_w1h[(size_t)HD*HD];                             // W1   s=6
__device__ h16  g_wqkth[(size_t)HD*HD];                           // (Wq^T Wk)^T s=6
__device__ h16  g_m1th[(size_t)HD*HD];                            // (Wo Wv)^T   s=6
__device__ h16  g_wvfh[(size_t)HD*HD];                            // W1WoWv s=7
__device__ h16  g_th[(size_t)TOK*HD];                             // t s=1
__device__ h16  g_uth[(size_t)TOK*HD];                            // u^T s=2
__device__ float g_sc[(size_t)NB*SEQ*SEQ];
__device__ h16  g_ph[(size_t)NB*SEQ*SEQ];                         // P s=0
__device__ float g_w2s[HD];
__device__ double g_acc;

// ---------------- helpers -----------------------------------------------------
__device__ __forceinline__ uint32_t s2u(const void* p){
    uint32_t a;
    asm("{ .reg .u64 t; cvta.to.shared.u64 t, %1; cvt.u32.u64 %0, t; }" : "=r"(a) : "l"(p));
    return a;
}
__device__ __forceinline__ uint32_t pkh(h16 a, h16 b){
    __half2 t(a, b); return *reinterpret_cast<uint32_t*>(&t);
}

#define CPA(dst, src) asm volatile("cp.async.cg.shared.global [%0], [%1], 16;" \
    :: "r"(dst), "l"(src) : "memory")
#define CPA_COMMIT() asm volatile("cp.async.commit_group;" ::: "memory")

__device__ __forceinline__ void ldm4(uint32_t* r, uint32_t addr){
    asm volatile("ldmatrix.sync.aligned.m8n8.x4.shared.b16 {%0,%1,%2,%3}, [%4];"
        : "=r"(r[0]), "=r"(r[1]), "=r"(r[2]), "=r"(r[3]) : "r"(addr));
}
__device__ __forceinline__ void mma_f16(float* d, const uint32_t* a, const uint32_t* b){
    asm volatile(
        "mma.sync.aligned.m16n8k16.row.col.f32.f16.f16.f32 "
        "{%0,%1,%2,%3}, {%4,%5,%6,%7}, {%8,%9}, {%0,%1,%2,%3};"
        : "+f"(d[0]), "+f"(d[1]), "+f"(d[2]), "+f"(d[3])
        : "r"(a[0]), "r"(a[1]), "r"(a[2]), "r"(a[3]), "r"(b[0]), "r"(b[1]));
}

#define TILE_B   16384
#define STAGE_B  32768
#define NSTAGE   3
#define SMEM_TOT (NSTAGE*STAGE_B)    // 96KB -> 2 CTAs/SM

// ---------------- 1-term fp16 mma.sync GEMM ------------------------------------
// C[m,n] = oscale * sum_k A[m,k]*B[n,k]  (NT), K=2048, leading dims 2048.
// MODE 0: write fp16 Ch ; 1: fp32 Cf ; 2: sum(relu(C)*w2s) -> g_acc
template<int MODE>
__global__ void __launch_bounds__(256, 2) mma_gemm(
    const h16* __restrict__ Ah, const h16* __restrict__ Bh,
    h16* __restrict__ Ch, float* __restrict__ Cf,
    const float* __restrict__ w2s, float oscale,
    size_t sA, size_t sB, size_t sC)
{
    extern __shared__ char smem[];
    const uint32_t sb = s2u(smem);

    const int tid = threadIdx.x;
    const int l   = tid & 31;
    const int wid = tid >> 5;
    const int wm  = wid & 1;          // 2 warps along M (64 rows each)
    const int wn  = wid >> 1;         // 4 warps along N (32 cols each)
    const int bn  = blockIdx.x * BN;
    const int bm  = blockIdx.y * BM;
    const size_t zo = blockIdx.z;

    Ah += zo * sA;  Bh += zo * sB;

    // ---- producer (cp.async) addressing
    const int pr = tid >> 3;                 // 0..31
    const int pc = (tid & 7) * 16;           // byte col in 128B row
    const uint32_t pdst = (uint32_t)pr * 128u + ((uint32_t)pc ^ (((uint32_t)pr & 7u) << 4));
    const char* gAh = (const char*)(Ah + (size_t)(bm + pr) * KDIM) + pc;
    const char* gBh = (const char*)(Bh + (size_t)(bn + pr) * KDIM) + pc;

    // ---- consumer (ldmatrix) addressing
    const int ar    = wm * 64 + (l & 15);
    const int akoff = (l >> 4) * 16;
    const uint32_t xA = ((uint32_t)ar & 7u) << 4;
    const int br    = wn * 32 + (l & 7) + ((l >> 4) & 1) * 8;
    const int bkoff = ((l >> 3) & 1) * 16;
    const uint32_t xB = ((uint32_t)br & 7u) << 4;

    float acc[4][4][4];
    #pragma unroll
    for (int i = 0; i < 4; i++)
        #pragma unroll
        for (int j = 0; j < 4; j++)
            #pragma unroll
            for (int r = 0; r < 4; r++) acc[i][j][r] = 0.f;

    // ---- prologue: chunks 0,1 into bufs 0,1
    #pragma unroll
    for (int s = 0; s < NSTAGE - 1; s++){
        const uint32_t s0 = sb + (uint32_t)s * STAGE_B;
        const size_t ko = (size_t)s * 128;
        #pragma unroll
        for (int j = 0; j < 4; j++){
            const size_t go = (size_t)j * 131072 + ko;    // +32 rows
            CPA(s0 +          pdst + j*4096, gAh + go);
            CPA(s0 + TILE_B + pdst + j*4096, gBh + go);
        }
        CPA_COMMIT();
    }

    int bufc = 0;
    int bufp = NSTAGE - 1;
    #pragma unroll 1
    for (int i = 0; i < KITERS; i++){
        asm volatile("cp.async.wait_group 1;" ::: "memory");
        __syncthreads();

        // produce chunk i+2 into the just-freed buffer (after sync => safe)
        if (i + NSTAGE - 1 < KITERS){
            const uint32_t s0 = sb + (uint32_t)bufp * STAGE_B;
            const size_t ko = (size_t)(i + NSTAGE - 1) * 128;
            #pragma unroll
            for (int j = 0; j < 4; j++){
                const size_t go = (size_t)j * 131072 + ko;
                CPA(s0 +          pdst + j*4096, gAh + go);
                CPA(s0 + TILE_B + pdst + j*4096, gBh + go);
            }
        }
        CPA_COMMIT();   // always commit to keep group counting aligned

        const uint32_t s0 = sb + (uint32_t)bufc * STAGE_B;
        #pragma unroll
        for (int ks = 0; ks < 4; ks++){
            const uint32_t kb = (uint32_t)ks * 32;
            uint32_t ah[4][4];
            #pragma unroll
            for (int fm = 0; fm < 4; fm++){
                uint32_t ad = s0 + (uint32_t)(ar + fm*16) * 128u + ((kb + akoff) ^ xA);
                ldm4(ah[fm], ad);
            }
            uint32_t bh[2][4];
            #pragma unroll
            for (int p = 0; p < 2; p++){
                uint32_t bd = s0 + TILE_B + (uint32_t)(br + p*16) * 128u + ((kb + bkoff) ^ xB);
                ldm4(bh[p], bd);
            }
            #pragma unroll
            for (int fm = 0; fm < 4; fm++)
                #pragma unroll
                for (int fn = 0; fn < 4; fn++)
                    mma_f16(acc[fm][fn], ah[fm], &bh[fn >> 1][(fn & 1) * 2]);
        }

        bufc = (bufc + 1 == NSTAGE) ? 0 : bufc + 1;
        bufp = (bufp + 1 == NSTAGE) ? 0 : bufp + 1;
    }

    // ---- epilogue
    const int crow = l >> 2;
    const int ccol = (l & 3) * 2;
    double local = 0.0;

    #pragma unroll
    for (int fm = 0; fm < 4; fm++){
        #pragma unroll
        for (int fn = 0; fn < 4; fn++){
            const int m0 = bm + wm*64 + fm*16 + crow;
            const int n0 = bn + wn*32 + fn*8 + ccol;
            const float* c = acc[fm][fn];
            if (MODE == 1){
                float* base = Cf + zo*sC;
                *(float2*)(base + (size_t)m0 * KDIM + n0)
                    = make_float2(c[0]*oscale, c[1]*oscale);
                *(float2*)(base + (size_t)(m0+8) * KDIM + n0)
                    = make_float2(c[2]*oscale, c[3]*oscale);
            } else if (MODE == 0){
                const size_t o0 = zo*sC + (size_t)m0 * KDIM + n0;
                const size_t o1 = zo*sC + (size_t)(m0+8) * KDIM + n0;
                *(uint32_t*)(Ch + o0) = pkh(__float2half_rn(c[0]*oscale),
                                            __float2half_rn(c[1]*oscale));
                *(uint32_t*)(Ch + o1) = pkh(__float2half_rn(c[2]*oscale),
                                            __float2half_rn(c[3]*oscale));
            } else {
                float w0 = w2s[n0], w1 = w2s[n0+1];
                float z;
                z = c[0]*oscale; local += (double)((z > 0.f ? z : 0.f) * w0);
                z = c[1]*oscale; local += (double)((z > 0.f ? z : 0.f) * w1);
                z = c[2]*oscale; local += (double)((z > 0.f ? z : 0.f) * w0);
                z = c[3]*oscale; local += (double)((z > 0.f ? z : 0.f) * w1);
            }
        }
    }

    if (MODE == 2){
        __syncthreads();
        double* red = (double*)smem;
        red[tid] = local;
        __syncthreads();
        #pragma unroll
        for (int s = 128; s > 0; s >>= 1){
            if (tid < s) red[tid] += red[tid + s];
            __syncthreads();
        }
        if (tid == 0) atomicAdd(&g_acc, red[0]);
    }
}

// ---------------- aux kernels -------------------------------------------------
__global__ void chalf_k(const float4* __restrict__ in, uint2* __restrict__ oh,
                        float scale)
{
    size_t i = (size_t)blockIdx.x * 256 + threadIdx.x;
    float4 f = in[i];
    oh[i] = make_uint2(pkh(__float2half_rn(f.x*scale), __float2half_rn(f.y*scale)),
                       pkh(__float2half_rn(f.z*scale), __float2half_rn(f.w*scale)));
}

// out[C][R] = in[R][C] * scale (fp16 hi); grid (C/32, R/32), block (32,8)
__global__ void thalf_k(const float* __restrict__ in, h16* __restrict__ oh,
                        int R, int C, float scale)
{
    __shared__ float t[32][33];
    int c0 = blockIdx.x * 32, r0 = blockIdx.y * 32;
    int tx = threadIdx.x, ty = threadIdx.y;
    #pragma unroll
    for (int j = 0; j < 32; j += 8)
        t[ty + j][tx] = in[(size_t)(r0 + ty + j) * C + c0 + tx];
    __syncthreads();
    #pragma unroll
    for (int j = 0; j < 32; j += 8){
        size_t o = (size_t)(c0 + ty + j) * R + r0 + tx;
        oh[o] = __float2half_rn(t[tx][ty + j] * scale);
    }
}

__global__ void softmax_k(const float* __restrict__ S, h16* __restrict__ Ph)
{
    const float* row = S + (size_t)blockIdx.x * SEQ;
    h16* ph = Ph + (size_t)blockIdx.x * SEQ;
    const int tid = threadIdx.x;  // 256
    __shared__ float sm[256];

    float v[8];
    float mx = -3.0e38f;
    #pragma unroll
    for (int t = 0; t < 8; t++){ v[t] = row[tid + 256*t]; mx = fmaxf(mx, v[t]); }
    sm[tid] = mx; __syncthreads();
    #pragma unroll
    for (int s = 128; s > 0; s >>= 1){
        if (tid < s) sm[tid] = fmaxf(sm[tid], sm[tid + s]);
        __syncthreads();
    }
    mx = sm[0]; __syncthreads();

    float sum = 0.f;
    #pragma unroll
    for (int t = 0; t < 8; t++){ v[t] = expf(v[t] - mx); sum += v[t]; }
    sm[tid] = sum; __syncthreads();
    #pragma unroll
    for (int s = 128; s > 0; s >>= 1){
        if (tid < s) sm[tid] += sm[tid + s];
        __syncthreads();
    }
    float inv = 1.0f / sm[0];
    #pragma unroll
    for (int t = 0; t < 8; t++)
        ph[tid + 256*t] = __float2half_rn(v[t] * inv);
}

__global__ void w2sum_k(const float* __restrict__ W2)
{
    int e = blockIdx.x * 256 + threadIdx.x;
    if (e == 0) g_acc = 0.0;
    float s = 0.f;
    for (int d = 0; d < HD; d++) s += W2[(size_t)d * HD + e];
    g_w2s[e] = s;
}

__global__ void out_k(float* __restrict__ out){ out[0] = (float)g_acc; }

// ---------------- launch --------------------------------------------------------
extern "C" void kernel_launch(void* const* d_in, const int* in_sizes, int n_in,
                              void* d_out, int out_size)
{
    const float* x  = (const float*)d_in[0];
    const float* Wq = (const float*)d_in[1];
    const float* Wk = (const float*)d_in[2];
    const float* Wv = (const float*)d_in[3];
    const float* Wo = (const float*)d_in[4];
    const float* W1 = (const float*)d_in[5];
    const float* W2 = (const float*)d_in[6];

    cudaFuncSetAttribute(mma_gemm<0>, cudaFuncAttributeMaxDynamicSharedMemorySize, SMEM_TOT);
    cudaFuncSetAttribute(mma_gemm<1>, cudaFuncAttributeMaxDynamicSharedMemorySize, SMEM_TOT);
    cudaFuncSetAttribute(mma_gemm<2>, cudaFuncAttributeMaxDynamicSharedMemorySize, SMEM_TOT);

    h16 *xh,*wqth,*wkth,*wvth,*woh,*w1h,*wqkth,*m1th,*wvfh,*th,*uth,*ph;
    float *sc,*w2s;
    cudaGetSymbolAddress((void**)&xh, g_xh);
    cudaGetSymbolAddress((void**)&wqth, g_wqth);
    cudaGetSymbolAddress((void**)&wkth, g_wkth);
    cudaGetSymbolAddress((void**)&wvth, g_wvth);
    cudaGetSymbolAddress((void**)&woh, g_woh);
    cudaGetSymbolAddress((void**)&w1h, g_w1h);
    cudaGetSymbolAddress((void**)&wqkth, g_wqkth);
    cudaGetSymbolAddress((void**)&m1th, g_m1th);
    cudaGetSymbolAddress((void**)&wvfh, g_wvfh);
    cudaGetSymbolAddress((void**)&th, g_th);
    cudaGetSymbolAddress((void**)&uth, g_uth);
    cudaGetSymbolAddress((void**)&ph, g_ph);
    cudaGetSymbolAddress((void**)&sc, g_sc);
    cudaGetSymbolAddress((void**)&w2s, g_w2s);

    const size_t SH = (size_t)SEQ * HD;
    const size_t SS = (size_t)SEQ * SEQ;
    const float WS = 64.0f;           // weight pre-scale 2^6
    dim3 t8(32, 8);
    dim3 gW(HD/BN, HD/BM, 1);

    w2sum_k<<<HD/256, 256>>>(W2);

    // inputs -> fp16 hi-only (scaled)
    chalf_k<<<(int)((size_t)TOK*HD/1024), 256>>>((const float4*)x,  (uint2*)xh, 1.0f);
    chalf_k<<<HD*HD/1024, 256>>>((const float4*)Wo, (uint2*)woh, WS);
    chalf_k<<<HD*HD/1024, 256>>>((const float4*)W1, (uint2*)w1h, WS);
    thalf_k<<<dim3(HD/32, HD/32, 1), t8>>>(Wq, wqth, HD, HD, WS);
    thalf_k<<<dim3(HD/32, HD/32, 1), t8>>>(Wk, wkth, HD, HD, WS);
    thalf_k<<<dim3(HD/32, HD/32, 1), t8>>>(Wv, wvth, HD, HD, WS);

    // -------- score path: score = x (Wq^T Wk) x^T --------
    // Wqkt = NT(Wk^T, Wq^T); store s=6: os=2^(6-12)
    mma_gemm<0><<<gW, 256, SMEM_TOT>>>(wkth, wqth, wqkth, nullptr, nullptr,
                                       0.015625f, 0,0,0);
    // t = NT(x, Wqkt); store s=1: os=2^(1-0-6)
    dim3 gT(HD/BN, TOK/BM, 1);
    mma_gemm<0><<<gT, 256, SMEM_TOT>>>(xh, wqkth, th, nullptr, nullptr,
                                       0.03125f, 0,0,0);
    // score[b] = NT(t[b], x[b]) fp32; os=2^(0-1-0)
    dim3 gSc(SEQ/BN, SEQ/BM, NB);
    mma_gemm<1><<<gSc, 256, SMEM_TOT>>>(th, xh, nullptr, sc, nullptr,
                                        0.5f, SH, SH, SS);

    softmax_k<<<NB*SEQ, 256>>>(sc, ph);

    // -------- value path: Z = P (x Wvf^T), Wvf = W1 Wo Wv --------
    // M1t = NT(Wv^T, Wo); store s=6: os=2^(6-12)
    mma_gemm<0><<<gW, 256, SMEM_TOT>>>(wvth, woh, m1th, nullptr, nullptr,
                                       0.015625f, 0,0,0);
    // Wvf = NT(W1, M1t); store s=7: os=2^(7-12)
    mma_gemm<0><<<gW, 256, SMEM_TOT>>>(w1h, m1th, wvfh, nullptr, nullptr,
                                       0.03125f, 0,0,0);
    // uT[b] = NT(Wvf, x[b]); store s=2: os=2^(2-7)
    dim3 gU(SEQ/BN, HD/BM, NB);
    mma_gemm<0><<<gU, 256, SMEM_TOT>>>(wvfh, xh, uth, nullptr, nullptr,
                                       0.03125f, 0, SH, SH);
    // Z[b] = NT(P[b], uT[b]) reduce; os=2^(0-0-2)
    dim3 gZ(HD/BN, SEQ/BM, NB);
    mma_gemm<2><<<gZ, 256, SMEM_TOT>>>(ph, uth, nullptr, nullptr, w2s,
                                       0.25f, SS, SH, 0);

    out_k<<<1,1>>>((float*)d_out);
}